// round 8
// baseline (speedup 1.0000x reference)
#include <cuda_runtime.h>
#include <cuda_bf16.h>
#include <stdint.h>
#include <math.h>

// VectorQuantizer: z [65536,256] f32, W [1024,256] f32.
// dist = ||z||^2 - 2 z.W^T + ||w||^2 ; idx = argmin (first-min tie-break)
// out (f32): z_q_st [N*256] | loss [N] | idx [N]
//
// HMMA (mma.sync bf16, exact 3-way split, 6 cross pairs, K'=1536) computes
// all dists + per-token best & second-best. Tokens with gap < TAU are
// re-resolved exactly in fp32 (identical arithmetic/order to the proven
// round-1 kernel). tcgen05 unavailable (harness compiles at compute_103).

#define D    256
#define K3   768            // 3 bf16 split blocks of 256
#define ROWB 1536           // bytes per split row (768 * 2)
#define NTOK 65536
#define NE   1024
#define TAU  1e-4f

__device__ float g_A[NTOK];
__device__ float g_C[NE];
__device__ int   g_idx[NTOK];
__device__ int   g_nflag;
__device__ int   g_flag[NTOK];
__device__ __align__(256) __nv_bfloat16 g_Az[(size_t)NTOK * K3];
__device__ __align__(256) __nv_bfloat16 g_Bw[(size_t)NE * K3];

// smem: A resident 12 regions x 16KB (SW128), then 2 B slab buffers x 16KB
#define SM_B   196608
#define SM_TOT 229376
#define SWZ(o) ((o) ^ (((o) >> 3) & 0x70))

__device__ __forceinline__ uint32_t smem_u32(const void* p) {
    uint32_t a;
    asm("{ .reg .u64 t; cvta.to.shared.u64 t, %1; cvt.u32.u64 %0, t; }" : "=r"(a) : "l"(p));
    return a;
}
__device__ __forceinline__ void cp_async16(uint32_t dst, const void* src) {
    asm volatile("cp.async.cg.shared.global [%0], [%1], 16;" :: "r"(dst), "l"(src) : "memory");
}
__device__ __forceinline__ void ldsm4(uint32_t a, uint32_t r[4]) {
    asm volatile("ldmatrix.sync.aligned.m8n8.x4.shared.b16 {%0,%1,%2,%3}, [%4];"
                 : "=r"(r[0]), "=r"(r[1]), "=r"(r[2]), "=r"(r[3]) : "r"(a));
}
__device__ __forceinline__ void mma_bf16(float d[4], const uint32_t a[4],
                                         uint32_t b0, uint32_t b1) {
    asm volatile(
        "mma.sync.aligned.m16n8k16.row.col.f32.bf16.bf16.f32 "
        "{%0,%1,%2,%3}, {%4,%5,%6,%7}, {%8,%9}, {%0,%1,%2,%3};"
        : "+f"(d[0]), "+f"(d[1]), "+f"(d[2]), "+f"(d[3])
        : "r"(a[0]), "r"(a[1]), "r"(a[2]), "r"(a[3]), "r"(b0), "r"(b1));
}

__global__ void reset_kernel() { g_nflag = 0; }

// ---------------------------------------------------------------------------
// Exact 3-way bf16 split: x -> [h1|h2|h3] blocks of 256 along K'.
// ---------------------------------------------------------------------------
__global__ void split_kernel(const float* __restrict__ x, int rows, int which) {
    __nv_bfloat16* dst = which ? g_Az : g_Bw;
    int idx4 = blockIdx.x * blockDim.x + threadIdx.x;   // one float4 each
    if (idx4 >= rows * 64) return;
    int r = idx4 >> 6, q = idx4 & 63;
    float4 v = *(const float4*)&x[(size_t)r * D + q * 4];
    float vv[4] = {v.x, v.y, v.z, v.w};
    union { __nv_bfloat16 h[4]; uint2 u; } p1, p2, p3;
    #pragma unroll
    for (int i = 0; i < 4; ++i) {
        float f = vv[i];
        p1.h[i] = __float2bfloat16(f);
        float r1 = __fadd_rn(f, -__bfloat162float(p1.h[i]));   // exact
        p2.h[i] = __float2bfloat16(r1);
        float r2 = __fadd_rn(r1, -__bfloat162float(p2.h[i]));  // exact
        p3.h[i] = __float2bfloat16(r2);
    }
    size_t rb = (size_t)r * K3 + q * 4;
    *(uint2*)&dst[rb +   0] = p1.u;
    *(uint2*)&dst[rb + 256] = p2.u;
    *(uint2*)&dst[rb + 512] = p3.u;
}

// ---------------------------------------------------------------------------
// Row sum-of-squares, strictly sequential fp32 (reference order).
// ---------------------------------------------------------------------------
__global__ void sumsq_kernel(const float* __restrict__ x, int which) {
    __shared__ float buf[32][257];
    int r0 = blockIdx.x * 32;
    for (int i = threadIdx.x; i < 32 * 256; i += 256) {
        int r = i >> 8, c = i & 255;
        buf[r][c] = x[(size_t)(r0 + r) * D + c];
    }
    __syncthreads();
    if (threadIdx.x < 32) {
        int r = threadIdx.x;
        float a = 0.0f;
        #pragma unroll 1
        for (int c = 0; c < 256; ++c) {
            float v = buf[r][c];
            a = __fadd_rn(a, __fmul_rn(v, v));
        }
        if (which) g_A[r0 + r] = a;
        else       g_C[r0 + r] = a;
    }
}

// ---------------------------------------------------------------------------
// B slab loader: slab u covers chunk n = u/24, pair p = (u%24)/4, ks = u%4.
// pair tables: a-block {0,0,1,1,0,2}, b-block {0,1,0,1,2,0}
// ---------------------------------------------------------------------------
__device__ __forceinline__ void load_Bslab(uint32_t sb, int u, int tid) {
    int s = u % 24, n = u / 24;
    int p = s >> 2, ks = s & 3;
    int pb = (int)((0x021010u >> (p * 4)) & 0xFu);
    size_t src0 = (size_t)(n * 128) * ROWB + pb * 512 + ks * 128;
    uint32_t dst0 = sb + SM_B + (u & 1) * 16384;
    #pragma unroll
    for (int it = 0; it < 4; ++it) {
        int i = tid + it * 256;
        int row = i >> 3, sub = i & 7;
        cp_async16(dst0 + SWZ(row * 128 + sub * 16),
                   (const char*)g_Bw + src0 + (size_t)row * ROWB + sub * 16);
    }
}

// ---------------------------------------------------------------------------
// Fused HMMA GEMM + argmin (+ second-best for ambiguity flagging).
// CTA = 128 tokens, 256 threads (4x2 warps). A resident; B double-buffered.
// ---------------------------------------------------------------------------
__global__ void __launch_bounds__(256, 1)
vq_hmma_kernel(int nch) {
    extern __shared__ __align__(1024) char smem[];
    uint32_t sb = smem_u32(smem);
    const int tid = threadIdx.x;
    const int l   = tid & 31, w = tid >> 5;
    const int wm  = w >> 1,  wn = w & 1;
    const int bt0 = blockIdx.x * 128;
    const int nslab = nch * 24;

    // load full A (12 regions x 128 rows x 128B)
    for (int i = tid; i < 12288; i += 256) {
        int r = i >> 10, rem = i & 1023;
        int row = rem >> 3, sub = rem & 7;
        cp_async16(sb + r * 16384 + SWZ(row * 128 + sub * 16),
                   (const char*)g_Az + (size_t)(bt0 + row) * ROWB + r * 128 + sub * 16);
    }
    asm volatile("cp.async.commit_group;" ::: "memory");
    load_Bslab(sb, 0, tid);
    asm volatile("cp.async.commit_group;" ::: "memory");
    load_Bslab(sb, 1, tid);
    asm volatile("cp.async.commit_group;" ::: "memory");

    float Ar[2][2];
    #pragma unroll
    for (int mt = 0; mt < 2; ++mt)
        #pragma unroll
        for (int h = 0; h < 2; ++h)
            Ar[mt][h] = g_A[bt0 + wm * 32 + mt * 16 + h * 8 + (l >> 2)];

    float bd[2][2], bd2[2][2];
    int   bi[2][2];
    #pragma unroll
    for (int mt = 0; mt < 2; ++mt)
        #pragma unroll
        for (int h = 0; h < 2; ++h) {
            bd[mt][h] = __int_as_float(0x7f800000);
            bd2[mt][h] = __int_as_float(0x7f800000);
            bi[mt][h] = 0;
        }

    float acc[2][8][4];
    #pragma unroll
    for (int mt = 0; mt < 2; ++mt)
        #pragma unroll
        for (int nt = 0; nt < 8; ++nt)
            #pragma unroll
            for (int e = 0; e < 4; ++e) acc[mt][nt][e] = 0.0f;

    for (int u = 0; u < nslab; ++u) {
        if (u + 2 < nslab)
            asm volatile("cp.async.wait_group 1;" ::: "memory");
        else
            asm volatile("cp.async.wait_group 0;" ::: "memory");
        __syncthreads();

        const int s = u % 24, n = u / 24;
        const int p = s >> 2, ks = s & 3;
        const int pa = (int)((0x201100u >> (p * 4)) & 0xFu);
        const uint32_t abase = sb + (pa * 4 + ks) * 16384;
        const uint32_t bbase = sb + SM_B + (u & 1) * 16384;

        #pragma unroll
        for (int kq = 0; kq < 2; ++kq) {
            uint32_t Bk[8][4];
            #pragma unroll
            for (int nt = 0; nt < 8; ++nt) {
                uint32_t ba = bbase +
                    SWZ((wn * 64 + nt * 8 + (l & 7)) * 128 + kq * 64 + (l >> 3) * 16);
                ldsm4(ba, Bk[nt]);
            }
            uint32_t Aa[2][2][4];
            #pragma unroll
            for (int mt = 0; mt < 2; ++mt)
                #pragma unroll
                for (int kk = 0; kk < 2; ++kk) {
                    uint32_t aa = abase +
                        SWZ((wm * 32 + mt * 16 + (l & 15)) * 128
                            + kq * 64 + kk * 32 + (l >> 4) * 16);
                    ldsm4(aa, Aa[mt][kk]);
                }
            #pragma unroll
            for (int mt = 0; mt < 2; ++mt)
                #pragma unroll
                for (int nt = 0; nt < 8; ++nt) {
                    mma_bf16(acc[mt][nt], Aa[mt][0], Bk[nt][0], Bk[nt][1]);
                    mma_bf16(acc[mt][nt], Aa[mt][1], Bk[nt][2], Bk[nt][3]);
                }
        }

        if (s == 23) {
            // chunk epilogue: dist = fl(fl(A - 2d) + C), first-min + 2nd-best
            #pragma unroll
            for (int mt = 0; mt < 2; ++mt)
                #pragma unroll
                for (int h = 0; h < 2; ++h)
                    #pragma unroll
                    for (int nt = 0; nt < 8; ++nt) {
                        int c0 = n * 128 + wn * 64 + nt * 8 + (l & 3) * 2;
                        float C0 = __ldg(&g_C[c0]);
                        float C1 = __ldg(&g_C[c0 + 1]);
                        float q0 = __fadd_rn(__fadd_rn(Ar[mt][h], -2.0f * acc[mt][nt][h * 2 + 0]), C0);
                        if (q0 < bd[mt][h]) { bd2[mt][h] = bd[mt][h]; bd[mt][h] = q0; bi[mt][h] = c0; }
                        else if (q0 < bd2[mt][h]) bd2[mt][h] = q0;
                        float q1 = __fadd_rn(__fadd_rn(Ar[mt][h], -2.0f * acc[mt][nt][h * 2 + 1]), C1);
                        if (q1 < bd[mt][h]) { bd2[mt][h] = bd[mt][h]; bd[mt][h] = q1; bi[mt][h] = c0 + 1; }
                        else if (q1 < bd2[mt][h]) bd2[mt][h] = q1;
                    }
            #pragma unroll
            for (int mt = 0; mt < 2; ++mt)
                #pragma unroll
                for (int nt = 0; nt < 8; ++nt)
                    #pragma unroll
                    for (int e = 0; e < 4; ++e) acc[mt][nt][e] = 0.0f;
        }
        __syncthreads();
        if (u + 2 < nslab) {
            load_Bslab(sb, u + 2, tid);
            asm volatile("cp.async.commit_group;" ::: "memory");
        }
    }

    // cross-lane reduce over the 4 lanes sharing each token row
    #pragma unroll
    for (int mt = 0; mt < 2; ++mt)
        #pragma unroll
        for (int h = 0; h < 2; ++h)
            #pragma unroll
            for (int off = 1; off <= 2; off <<= 1) {
                float od  = __shfl_xor_sync(0xffffffffu, bd[mt][h], off);
                int   oi  = __shfl_xor_sync(0xffffffffu, bi[mt][h], off);
                float od2 = __shfl_xor_sync(0xffffffffu, bd2[mt][h], off);
                float mx  = fmaxf(bd[mt][h], od);
                bd2[mt][h] = fminf(fminf(bd2[mt][h], od2), mx);
                if (od < bd[mt][h] || (od == bd[mt][h] && oi < bi[mt][h])) {
                    bd[mt][h] = od; bi[mt][h] = oi;
                }
            }

    __syncthreads();                     // B buffers dead; reuse for staging
    float* stD  = (float*)(smem + SM_B);
    int*   stI  = (int*)(smem + SM_B + 2048);
    float* stD2 = (float*)(smem + SM_B + 4096);
    if ((l & 3) == 0) {
        #pragma unroll
        for (int mt = 0; mt < 2; ++mt)
            #pragma unroll
            for (int h = 0; h < 2; ++h) {
                int t = wm * 32 + mt * 16 + h * 8 + (l >> 2);
                stD[t * 2 + wn]  = bd[mt][h];
                stI[t * 2 + wn]  = bi[mt][h];
                stD2[t * 2 + wn] = bd2[mt][h];
            }
    }
    __syncthreads();
    if (tid < 128) {
        float d0 = stD[tid * 2], d1 = stD[tid * 2 + 1];
        int   i0 = stI[tid * 2], i1 = stI[tid * 2 + 1];
        float s2 = fminf(fminf(stD2[tid * 2], stD2[tid * 2 + 1]), fmaxf(d0, d1));
        float db = d0; int ib = i0;
        if (d1 < d0 || (d1 == d0 && i1 < i0)) { db = d1; ib = i1; }
        g_idx[bt0 + tid] = ib;
        if (s2 - db < TAU) {                      // ambiguous: exact re-check
            int pos = atomicAdd(&g_nflag, 1);
            g_flag[pos] = bt0 + tid;
        }
    }
}

// ---------------------------------------------------------------------------
// Exact fp32 refinement for flagged tokens. One token per block iteration;
// per-code dot is a sequential k-ascending FMA chain + identical epilogue
// rounding to the proven round-1 fp32 kernel. First-min tie-break.
// ---------------------------------------------------------------------------
__global__ void __launch_bounds__(128, 1)
vq_refine_kernel(const float* __restrict__ z, const float* __restrict__ w) {
    extern __shared__ __align__(16) float sref[];
    float* sW = sref;                 // 128 rows x stride 257 (bank-skewed)
    float* zr = sW + 128 * 257;       // 256 floats
    float* rd = zr + 256;             // 4 warp partials
    int*   ri = (int*)(rd + 4);

    const int tid = threadIdx.x, lane = tid & 31, wid = tid >> 5;
    const int nf = g_nflag;

    for (int it = blockIdx.x; it < nf; it += gridDim.x) {
        const int t = g_flag[it];
        __syncthreads();              // previous iteration readers done
        for (int i = tid; i < 256; i += 128) zr[i] = z[(size_t)t * D + i];
        const float A = g_A[t];
        float bdl = __int_as_float(0x7f800000);
        int   bil = 0x7fffffff;

        for (int c0 = 0; c0 < NE; c0 += 128) {
            __syncthreads();
            for (int i = tid; i < 128 * 64; i += 128) {
                int row = i >> 6, q = (i & 63) * 4;
                float4 v = *(const float4*)&w[(size_t)(c0 + row) * D + q];
                float* dstr = sW + row * 257 + q;
                dstr[0] = v.x; dstr[1] = v.y; dstr[2] = v.z; dstr[3] = v.w;
            }
            __syncthreads();
            const float* wr = sW + tid * 257;
            float acc = 0.0f;
            #pragma unroll 8
            for (int k = 0; k < 256; ++k)
                acc = fmaf(zr[k], wr[k], acc);     // sequential, k ascending
            int c = c0 + tid;                      // ascending across chunks
            float dist = __fadd_rn(__fadd_rn(A, -2.0f * acc), __ldg(&g_C[c]));
            if (dist < bdl) { bdl = dist; bil = c; }
        }

        // 128-thread first-min reduce
        #pragma unroll
        for (int off = 16; off > 0; off >>= 1) {
            float od = __shfl_xor_sync(0xffffffffu, bdl, off);
            int   oi = __shfl_xor_sync(0xffffffffu, bil, off);
            if (od < bdl || (od == bdl && oi < bil)) { bdl = od; bil = oi; }
        }
        if (lane == 0) { rd[wid] = bdl; ri[wid] = bil; }
        __syncthreads();
        if (tid == 0) {
            float b = rd[0]; int v = ri[0];
            #pragma unroll
            for (int m = 1; m < 4; ++m) {
                if (rd[m] < b || (rd[m] == b && ri[m] < v)) { b = rd[m]; v = ri[m]; }
            }
            g_idx[t] = v;
        }
    }
}

// ---------------------------------------------------------------------------
// Output: warp per token. z_q_st = fl(z + fl(zq-z)); loss = fl(m + fl(.25m))
// ---------------------------------------------------------------------------
__global__ void vq_out_kernel(const float* __restrict__ z, const float* __restrict__ w,
                              float* __restrict__ out_zq, float* __restrict__ out_loss,
                              float* __restrict__ out_idx) {
    int warp = threadIdx.x >> 5, lane = threadIdx.x & 31;
    int t = blockIdx.x * 8 + warp;
    int j = g_idx[t];
    const float4* zp = (const float4*)(z + (size_t)t * D);
    const float4* wp = (const float4*)(w + (size_t)j * D);
    float4* op = (float4*)(out_zq + (size_t)t * D);
    float sq = 0.0f;
    #pragma unroll
    for (int i = 0; i < 2; ++i) {
        float4 zv = zp[lane + 32 * i];
        float4 wv = wp[lane + 32 * i];
        float4 o;
        float d;
        d = __fadd_rn(wv.x, -zv.x); o.x = __fadd_rn(zv.x, d); sq = __fadd_rn(sq, __fmul_rn(d, d));
        d = __fadd_rn(wv.y, -zv.y); o.y = __fadd_rn(zv.y, d); sq = __fadd_rn(sq, __fmul_rn(d, d));
        d = __fadd_rn(wv.z, -zv.z); o.z = __fadd_rn(zv.z, d); sq = __fadd_rn(sq, __fmul_rn(d, d));
        d = __fadd_rn(wv.w, -zv.w); o.w = __fadd_rn(zv.w, d); sq = __fadd_rn(sq, __fmul_rn(d, d));
        op[lane + 32 * i] = o;
    }
    #pragma unroll
    for (int o = 16; o > 0; o >>= 1) sq += __shfl_xor_sync(0xffffffffu, sq, o);
    if (lane == 0) {
        float m = sq * (1.0f / 256.0f);
        out_loss[t] = __fadd_rn(m, __fmul_rn(0.25f, m));
        out_idx[t]  = (float)j;
    }
}

// ---------------------------------------------------------------------------
extern "C" void kernel_launch(void* const* d_in, const int* in_sizes, int n_in,
                              void* d_out, int out_size) {
    const float* z = (const float*)d_in[0];
    const float* w = (const float*)d_in[1];
    const int n  = in_sizes[0] / D;   // 65536
    const int ne = in_sizes[1] / D;   // 1024
    float* out      = (float*)d_out;
    float* out_loss = out + (size_t)n * D;
    float* out_idx  = out_loss + n;

    reset_kernel<<<1, 1>>>();
    split_kernel<<<(n * 64) / 256, 256>>>(z, n, 1);
    split_kernel<<<(ne * 64 + 255) / 256, 256>>>(w, ne, 0);
    sumsq_kernel<<<n / 32, 256>>>(z, 1);
    sumsq_kernel<<<ne / 32, 256>>>(w, 0);

    cudaFuncSetAttribute(vq_hmma_kernel,
                         cudaFuncAttributeMaxDynamicSharedMemorySize, SM_TOT);
    vq_hmma_kernel<<<n / 128, 256, SM_TOT>>>(ne / 128);

    const int refine_smem = (128 * 257 + 256 + 8) * 4;
    cudaFuncSetAttribute(vq_refine_kernel,
                         cudaFuncAttributeMaxDynamicSharedMemorySize, refine_smem);
    vq_refine_kernel<<<512, 128, refine_smem>>>(z, w);

    vq_out_kernel<<<n / 8, 256>>>(z, w, out, out_loss, out_idx);
}

// round 9
// speedup vs baseline: 1.3805x; 1.3805x over previous
#include <cuda_runtime.h>
#include <cuda_bf16.h>
#include <stdint.h>
#include <math.h>

// VectorQuantizer: z [65536,256] f32, W [1024,256] f32.
// dist = ||z||^2 - 2 z.W^T + ||w||^2 ; idx = argmin (first-min tie-break)
// out (f32): z_q_st [N*256] | loss [N] | idx [N]
//
// HMMA (mma.sync bf16) with 2-way exact split, 3 cross pairs (z1w1, z1w2,
// z2w1; K'=768). Worst-case dist error ~1.1e-5 << TAU; tokens with
// best/second gap < TAU are re-resolved exactly in fp32 (identical
// arithmetic order to the proven round-1 kernel) so argmin matches fp32.

#define D    256
#define K2   512            // 2 bf16 split blocks of 256
#define ROWB 1024           // bytes per split row (512 * 2)
#define NTOK 65536
#define NE   1024
#define TAU  1e-4f

__device__ float g_A[NTOK];
__device__ float g_C[NE];
__device__ int   g_idx[NTOK];
__device__ int   g_nflag;
__device__ int   g_flag[NTOK];
__device__ __align__(256) __nv_bfloat16 g_Az[(size_t)NTOK * K2];
__device__ __align__(256) __nv_bfloat16 g_Bw[(size_t)NE * K2];

// smem: A resident 8 regions x 16KB (SW128) + B ring 4 x 16KB
#define SM_B   131072
#define SM_TOT 196608
#define SWZ(o) ((o) ^ (((o) >> 3) & 0x70))

__device__ __forceinline__ uint32_t smem_u32(const void* p) {
    uint32_t a;
    asm("{ .reg .u64 t; cvta.to.shared.u64 t, %1; cvt.u32.u64 %0, t; }" : "=r"(a) : "l"(p));
    return a;
}
__device__ __forceinline__ void cp_async16(uint32_t dst, const void* src) {
    asm volatile("cp.async.cg.shared.global [%0], [%1], 16;" :: "r"(dst), "l"(src) : "memory");
}
__device__ __forceinline__ void ldsm4(uint32_t a, uint32_t r[4]) {
    asm volatile("ldmatrix.sync.aligned.m8n8.x4.shared.b16 {%0,%1,%2,%3}, [%4];"
                 : "=r"(r[0]), "=r"(r[1]), "=r"(r[2]), "=r"(r[3]) : "r"(a));
}
__device__ __forceinline__ void mma_bf16(float d[4], const uint32_t a[4],
                                         uint32_t b0, uint32_t b1) {
    asm volatile(
        "mma.sync.aligned.m16n8k16.row.col.f32.bf16.bf16.f32 "
        "{%0,%1,%2,%3}, {%4,%5,%6,%7}, {%8,%9}, {%0,%1,%2,%3};"
        : "+f"(d[0]), "+f"(d[1]), "+f"(d[2]), "+f"(d[3])
        : "r"(a[0]), "r"(a[1]), "r"(a[2]), "r"(a[3]), "r"(b0), "r"(b1));
}

__global__ void reset_kernel() { g_nflag = 0; }

// ---------------------------------------------------------------------------
// Exact 2-way bf16 split: x -> [h1|h2] blocks of 256 along K'.
// ---------------------------------------------------------------------------
__global__ void split_kernel(const float* __restrict__ x, int rows, int which) {
    __nv_bfloat16* dst = which ? g_Az : g_Bw;
    int idx4 = blockIdx.x * blockDim.x + threadIdx.x;   // one float4 each
    if (idx4 >= rows * 64) return;
    int r = idx4 >> 6, q = idx4 & 63;
    float4 v = *(const float4*)&x[(size_t)r * D + q * 4];
    float vv[4] = {v.x, v.y, v.z, v.w};
    union { __nv_bfloat16 h[4]; uint2 u; } p1, p2;
    #pragma unroll
    for (int i = 0; i < 4; ++i) {
        float f = vv[i];
        p1.h[i] = __float2bfloat16(f);
        float r1 = __fadd_rn(f, -__bfloat162float(p1.h[i]));   // exact
        p2.h[i] = __float2bfloat16(r1);
    }
    size_t rb = (size_t)r * K2 + q * 4;
    *(uint2*)&dst[rb +   0] = p1.u;
    *(uint2*)&dst[rb + 256] = p2.u;
}

// ---------------------------------------------------------------------------
// Row sum-of-squares, strictly sequential fp32 (reference order).
// ---------------------------------------------------------------------------
__global__ void sumsq_kernel(const float* __restrict__ x, int which) {
    __shared__ float buf[32][257];
    int r0 = blockIdx.x * 32;
    for (int i = threadIdx.x; i < 32 * 256; i += 256) {
        int r = i >> 8, c = i & 255;
        buf[r][c] = x[(size_t)(r0 + r) * D + c];
    }
    __syncthreads();
    if (threadIdx.x < 32) {
        int r = threadIdx.x;
        float a = 0.0f;
        #pragma unroll 1
        for (int c = 0; c < 256; ++c) {
            float v = buf[r][c];
            a = __fadd_rn(a, __fmul_rn(v, v));
        }
        if (which) g_A[r0 + r] = a;
        else       g_C[r0 + r] = a;
    }
}

// ---------------------------------------------------------------------------
// B slab loader: slab u -> chunk n = u/12, s = u%12, pair p = s/4, ks = s%4.
// pair tables: a-block {0,0,1}, b-block {0,1,0}. 128 codes x 64 bf16, SW128.
// ---------------------------------------------------------------------------
__device__ __forceinline__ void load_Bslab(uint32_t sb, int u, int tid) {
    int s = u % 12, n = u / 12;
    int p = s >> 2, ks = s & 3;
    int pb = (int)((0x010u >> (p * 4)) & 0xFu);
    size_t src0 = (size_t)(n * 128) * ROWB + pb * 512 + ks * 128;
    uint32_t dst0 = sb + SM_B + (u & 3) * 16384;
    #pragma unroll
    for (int it = 0; it < 2; ++it) {                 // 1024 chunks / 512 thr
        int i = tid + it * 512;
        int row = i >> 3, sub = i & 7;
        cp_async16(dst0 + SWZ(row * 128 + sub * 16),
                   (const char*)g_Bw + src0 + (size_t)row * ROWB + sub * 16);
    }
}

// ---------------------------------------------------------------------------
// Fused HMMA GEMM + argmin (+ second-best flagging).
// CTA = 128 tokens, 512 threads (4x4 warps, 32x32 warp tiles).
// A resident (128KB); B 4-buffer ring, one barrier per slab.
// ---------------------------------------------------------------------------
__global__ void __launch_bounds__(512, 1)
vq_hmma_kernel(int nch) {
    extern __shared__ __align__(1024) char smem[];
    uint32_t sb = smem_u32(smem);
    const int tid = threadIdx.x;
    const int l   = tid & 31, w = tid >> 5;
    const int wm  = w >> 2,  wn = w & 3;
    const int bt0 = blockIdx.x * 128;
    const int nslab = nch * 12;

    // group 0: full A (8 regions x 128 rows x 128B) + B slab 0
    for (int i = tid; i < 8192; i += 512) {
        int r = i >> 10, rem = i & 1023;
        int row = rem >> 3, sub = rem & 7;
        cp_async16(sb + r * 16384 + SWZ(row * 128 + sub * 16),
                   (const char*)g_Az + (size_t)(bt0 + row) * ROWB + r * 128 + sub * 16);
    }
    load_Bslab(sb, 0, tid);
    asm volatile("cp.async.commit_group;" ::: "memory");
    load_Bslab(sb, 1, tid);
    asm volatile("cp.async.commit_group;" ::: "memory");
    load_Bslab(sb, 2, tid);
    asm volatile("cp.async.commit_group;" ::: "memory");

    float Ar[2][2];
    #pragma unroll
    for (int mt = 0; mt < 2; ++mt)
        #pragma unroll
        for (int h = 0; h < 2; ++h)
            Ar[mt][h] = g_A[bt0 + wm * 32 + mt * 16 + h * 8 + (l >> 2)];

    float bd[2][2], bd2[2][2];
    int   bi[2][2];
    #pragma unroll
    for (int mt = 0; mt < 2; ++mt)
        #pragma unroll
        for (int h = 0; h < 2; ++h) {
            bd[mt][h] = __int_as_float(0x7f800000);
            bd2[mt][h] = __int_as_float(0x7f800000);
            bi[mt][h] = 0;
        }

    float acc[2][4][4];
    #pragma unroll
    for (int mt = 0; mt < 2; ++mt)
        #pragma unroll
        for (int nt = 0; nt < 4; ++nt)
            #pragma unroll
            for (int e = 0; e < 4; ++e) acc[mt][nt][e] = 0.0f;

    for (int u = 0; u < nslab; ++u) {
        if (u + 3 < nslab)
            asm volatile("cp.async.wait_group 2;" ::: "memory");
        else
            asm volatile("cp.async.wait_group 0;" ::: "memory");
        __syncthreads();   // all warps finished compute on slab u-1's buffer

        if (u + 3 < nslab) {
            load_Bslab(sb, u + 3, tid);
            asm volatile("cp.async.commit_group;" ::: "memory");
        }

        const int s = u % 12, n = u / 12;
        const int p = s >> 2, ks = s & 3;
        const int pa = (int)((0x100u >> (p * 4)) & 0xFu);
        const uint32_t abase = sb + (pa * 4 + ks) * 16384;
        const uint32_t bbase = sb + SM_B + (u & 3) * 16384;

        #pragma unroll
        for (int kq = 0; kq < 2; ++kq) {
            uint32_t Bk[4][4];
            #pragma unroll
            for (int nt = 0; nt < 4; ++nt) {
                uint32_t ba = bbase +
                    SWZ((wn * 32 + nt * 8 + (l & 7)) * 128 + kq * 64 + (l >> 3) * 16);
                ldsm4(ba, Bk[nt]);
            }
            uint32_t Aa[2][2][4];
            #pragma unroll
            for (int mt = 0; mt < 2; ++mt)
                #pragma unroll
                for (int kk = 0; kk < 2; ++kk) {
                    uint32_t aa = abase +
                        SWZ((wm * 32 + mt * 16 + (l & 15)) * 128
                            + kq * 64 + kk * 32 + (l >> 4) * 16);
                    ldsm4(aa, Aa[mt][kk]);
                }
            #pragma unroll
            for (int mt = 0; mt < 2; ++mt)
                #pragma unroll
                for (int nt = 0; nt < 4; ++nt) {
                    mma_bf16(acc[mt][nt], Aa[mt][0], Bk[nt][0], Bk[nt][1]);
                    mma_bf16(acc[mt][nt], Aa[mt][1], Bk[nt][2], Bk[nt][3]);
                }
        }

        if (s == 11) {
            // chunk epilogue: dist = fl(fl(A - 2d) + C), first-min + 2nd-best
            #pragma unroll
            for (int mt = 0; mt < 2; ++mt)
                #pragma unroll
                for (int h = 0; h < 2; ++h)
                    #pragma unroll
                    for (int nt = 0; nt < 4; ++nt) {
                        int c0 = n * 128 + wn * 32 + nt * 8 + (l & 3) * 2;
                        float C0 = __ldg(&g_C[c0]);
                        float C1 = __ldg(&g_C[c0 + 1]);
                        float q0 = __fadd_rn(__fadd_rn(Ar[mt][h], -2.0f * acc[mt][nt][h * 2 + 0]), C0);
                        if (q0 < bd[mt][h]) { bd2[mt][h] = bd[mt][h]; bd[mt][h] = q0; bi[mt][h] = c0; }
                        else if (q0 < bd2[mt][h]) bd2[mt][h] = q0;
                        float q1 = __fadd_rn(__fadd_rn(Ar[mt][h], -2.0f * acc[mt][nt][h * 2 + 1]), C1);
                        if (q1 < bd[mt][h]) { bd2[mt][h] = bd[mt][h]; bd[mt][h] = q1; bi[mt][h] = c0 + 1; }
                        else if (q1 < bd2[mt][h]) bd2[mt][h] = q1;
                    }
            #pragma unroll
            for (int mt = 0; mt < 2; ++mt)
                #pragma unroll
                for (int nt = 0; nt < 4; ++nt)
                    #pragma unroll
                    for (int e = 0; e < 4; ++e) acc[mt][nt][e] = 0.0f;
        }
    }

    // cross-lane reduce over the 4 lanes sharing each token row
    #pragma unroll
    for (int mt = 0; mt < 2; ++mt)
        #pragma unroll
        for (int h = 0; h < 2; ++h)
            #pragma unroll
            for (int off = 1; off <= 2; off <<= 1) {
                float od  = __shfl_xor_sync(0xffffffffu, bd[mt][h], off);
                int   oi  = __shfl_xor_sync(0xffffffffu, bi[mt][h], off);
                float od2 = __shfl_xor_sync(0xffffffffu, bd2[mt][h], off);
                float mx  = fmaxf(bd[mt][h], od);
                bd2[mt][h] = fminf(fminf(bd2[mt][h], od2), mx);
                if (od < bd[mt][h] || (od == bd[mt][h] && oi < bi[mt][h])) {
                    bd[mt][h] = od; bi[mt][h] = oi;
                }
            }

    __syncthreads();                     // B ring dead; reuse for staging
    float* stD  = (float*)(smem + SM_B);
    int*   stI  = (int*)(smem + SM_B + 2048);
    float* stD2 = (float*)(smem + SM_B + 4096);
    if ((l & 3) == 0) {
        #pragma unroll
        for (int mt = 0; mt < 2; ++mt)
            #pragma unroll
            for (int h = 0; h < 2; ++h) {
                int t = wm * 32 + mt * 16 + h * 8 + (l >> 2);
                stD[t * 4 + wn]  = bd[mt][h];
                stI[t * 4 + wn]  = bi[mt][h];
                stD2[t * 4 + wn] = bd2[mt][h];
            }
    }
    __syncthreads();
    if (tid < 128) {
        float db = stD[tid * 4];
        int   ib = stI[tid * 4];
        float s2 = stD2[tid * 4];
        #pragma unroll
        for (int m = 1; m < 4; ++m) {
            float d = stD[tid * 4 + m];
            int   i = stI[tid * 4 + m];
            float d2 = stD2[tid * 4 + m];
            s2 = fminf(s2, d2);
            if (d < db || (d == db && i < ib)) { s2 = fminf(s2, db); db = d; ib = i; }
            else s2 = fminf(s2, d);
        }
        g_idx[bt0 + tid] = ib;
        if (s2 - db < TAU) {                      // ambiguous: exact re-check
            int pos = atomicAdd(&g_nflag, 1);
            g_flag[pos] = bt0 + tid;
        }
    }
}

// ---------------------------------------------------------------------------
// Exact fp32 refinement for flagged tokens (identical arithmetic order to
// the proven round-1 fp32 kernel). First-min tie-break.
// ---------------------------------------------------------------------------
__global__ void __launch_bounds__(128, 1)
vq_refine_kernel(const float* __restrict__ z, const float* __restrict__ w) {
    extern __shared__ __align__(16) float sref[];
    float* sW = sref;                 // 128 rows x stride 257 (bank-skewed)
    float* zr = sW + 128 * 257;       // 256 floats
    float* rd = zr + 256;             // 4 warp partials
    int*   ri = (int*)(rd + 4);

    const int tid = threadIdx.x, lane = tid & 31, wid = tid >> 5;
    const int nf = g_nflag;

    for (int it = blockIdx.x; it < nf; it += gridDim.x) {
        const int t = g_flag[it];
        __syncthreads();              // previous iteration readers done
        for (int i = tid; i < 256; i += 128) zr[i] = z[(size_t)t * D + i];
        const float A = g_A[t];
        float bdl = __int_as_float(0x7f800000);
        int   bil = 0x7fffffff;

        for (int c0 = 0; c0 < NE; c0 += 128) {
            __syncthreads();
            for (int i = tid; i < 128 * 64; i += 128) {
                int row = i >> 6, q = (i & 63) * 4;
                float4 v = *(const float4*)&w[(size_t)(c0 + row) * D + q];
                float* dstr = sW + row * 257 + q;
                dstr[0] = v.x; dstr[1] = v.y; dstr[2] = v.z; dstr[3] = v.w;
            }
            __syncthreads();
            const float* wr = sW + tid * 257;
            float acc = 0.0f;
            #pragma unroll 8
            for (int k = 0; k < 256; ++k)
                acc = fmaf(zr[k], wr[k], acc);     // sequential, k ascending
            int c = c0 + tid;                      // ascending across chunks
            float dist = __fadd_rn(__fadd_rn(A, -2.0f * acc), __ldg(&g_C[c]));
            if (dist < bdl) { bdl = dist; bil = c; }
        }

        #pragma unroll
        for (int off = 16; off > 0; off >>= 1) {
            float od = __shfl_xor_sync(0xffffffffu, bdl, off);
            int   oi = __shfl_xor_sync(0xffffffffu, bil, off);
            if (od < bdl || (od == bdl && oi < bil)) { bdl = od; bil = oi; }
        }
        if (lane == 0) { rd[wid] = bdl; ri[wid] = bil; }
        __syncthreads();
        if (tid == 0) {
            float b = rd[0]; int v = ri[0];
            #pragma unroll
            for (int m = 1; m < 4; ++m) {
                if (rd[m] < b || (rd[m] == b && ri[m] < v)) { b = rd[m]; v = ri[m]; }
            }
            g_idx[t] = v;
        }
    }
}

// ---------------------------------------------------------------------------
// Output: warp per token. z_q_st = fl(z + fl(zq-z)); loss = fl(m + fl(.25m))
// ---------------------------------------------------------------------------
__global__ void vq_out_kernel(const float* __restrict__ z, const float* __restrict__ w,
                              float* __restrict__ out_zq, float* __restrict__ out_loss,
                              float* __restrict__ out_idx) {
    int warp = threadIdx.x >> 5, lane = threadIdx.x & 31;
    int t = blockIdx.x * 8 + warp;
    int j = g_idx[t];
    const float4* zp = (const float4*)(z + (size_t)t * D);
    const float4* wp = (const float4*)(w + (size_t)j * D);
    float4* op = (float4*)(out_zq + (size_t)t * D);
    float sq = 0.0f;
    #pragma unroll
    for (int i = 0; i < 2; ++i) {
        float4 zv = zp[lane + 32 * i];
        float4 wv = wp[lane + 32 * i];
        float4 o;
        float d;
        d = __fadd_rn(wv.x, -zv.x); o.x = __fadd_rn(zv.x, d); sq = __fadd_rn(sq, __fmul_rn(d, d));
        d = __fadd_rn(wv.y, -zv.y); o.y = __fadd_rn(zv.y, d); sq = __fadd_rn(sq, __fmul_rn(d, d));
        d = __fadd_rn(wv.z, -zv.z); o.z = __fadd_rn(zv.z, d); sq = __fadd_rn(sq, __fmul_rn(d, d));
        d = __fadd_rn(wv.w, -zv.w); o.w = __fadd_rn(zv.w, d); sq = __fadd_rn(sq, __fmul_rn(d, d));
        op[lane + 32 * i] = o;
    }
    #pragma unroll
    for (int o = 16; o > 0; o >>= 1) sq += __shfl_xor_sync(0xffffffffu, sq, o);
    if (lane == 0) {
        float m = sq * (1.0f / 256.0f);
        out_loss[t] = __fadd_rn(m, __fmul_rn(0.25f, m));
        out_idx[t]  = (float)j;
    }
}

// ---------------------------------------------------------------------------
extern "C" void kernel_launch(void* const* d_in, const int* in_sizes, int n_in,
                              void* d_out, int out_size) {
    const float* z = (const float*)d_in[0];
    const float* w = (const float*)d_in[1];
    const int n  = in_sizes[0] / D;   // 65536
    const int ne = in_sizes[1] / D;   // 1024
    float* out      = (float*)d_out;
    float* out_loss = out + (size_t)n * D;
    float* out_idx  = out_loss + n;

    reset_kernel<<<1, 1>>>();
    split_kernel<<<(n * 64) / 256, 256>>>(z, n, 1);
    split_kernel<<<(ne * 64 + 255) / 256, 256>>>(w, ne, 0);
    sumsq_kernel<<<n / 32, 256>>>(z, 1);
    sumsq_kernel<<<ne / 32, 256>>>(w, 0);

    cudaFuncSetAttribute(vq_hmma_kernel,
                         cudaFuncAttributeMaxDynamicSharedMemorySize, SM_TOT);
    vq_hmma_kernel<<<n / 128, 512, SM_TOT>>>(ne / 128);

    const int refine_smem = (128 * 257 + 256 + 8) * 4;
    cudaFuncSetAttribute(vq_refine_kernel,
                         cudaFuncAttributeMaxDynamicSharedMemorySize, refine_smem);
    vq_refine_kernel<<<512, 128, refine_smem>>>(z, w);

    vq_out_kernel<<<n / 8, 256>>>(z, w, out, out_loss, out_idx);
}

// round 11
// speedup vs baseline: 1.9394x; 1.4048x over previous
#include <cuda_runtime.h>
#include <cuda_fp16.h>
#include <stdint.h>
#include <math.h>

// VectorQuantizer: z [65536,256] f32, W [1024,256] f32.
// dist = ||z||^2 - 2 z.W^T + ||w||^2 ; idx = argmin (first-min tie-break)
// out (f32): z_q_st [N*256] | loss [N] | idx [N]
//
// Single-pair fp16 HMMA (K=256, w scaled x1024 to dodge subnormals) computes
// approximate dists + per-token best/second-best. Worst-case dist error
// <= 2.7e-4 (|z|2<=21, |w|2<=0.01, fp16 eps 2^-12) so gap < TAU=7e-4 flags
// every token whose fp32 argmin could differ; those are re-resolved exactly
// in fp32 (identical arithmetic order to the proven round-1 kernel).

#define D    256
#define NTOK 65536
#define NE   1024
#define TAU  7e-4f

__device__ float g_A[NTOK];
__device__ float g_C[NE];
__device__ int   g_idx[NTOK];
__device__ int   g_nflag;
__device__ int   g_flag[NTOK];
__device__ __align__(256) __half g_Azh[(size_t)NTOK * D];
__device__ __align__(256) __half g_Bwh[(size_t)NE * D];

// smem: A resident 4 regions x 16KB (SW128) + B ring 4 x 16KB
#define SM_B   65536
#define SM_TOT 131072
#define SWZ(o) ((o) ^ (((o) >> 3) & 0x70))

__device__ __forceinline__ uint32_t smem_u32(const void* p) {
    uint32_t a;
    asm("{ .reg .u64 t; cvta.to.shared.u64 t, %1; cvt.u32.u64 %0, t; }" : "=r"(a) : "l"(p));
    return a;
}
__device__ __forceinline__ void cp_async16(uint32_t dst, const void* src) {
    asm volatile("cp.async.cg.shared.global [%0], [%1], 16;" :: "r"(dst), "l"(src) : "memory");
}
__device__ __forceinline__ void ldsm4(uint32_t a, uint32_t r[4]) {
    asm volatile("ldmatrix.sync.aligned.m8n8.x4.shared.b16 {%0,%1,%2,%3}, [%4];"
                 : "=r"(r[0]), "=r"(r[1]), "=r"(r[2]), "=r"(r[3]) : "r"(a));
}
__device__ __forceinline__ void mma_f16(float d[4], const uint32_t a[4],
                                        uint32_t b0, uint32_t b1) {
    asm volatile(
        "mma.sync.aligned.m16n8k16.row.col.f32.f16.f16.f32 "
        "{%0,%1,%2,%3}, {%4,%5,%6,%7}, {%8,%9}, {%0,%1,%2,%3};"
        : "+f"(d[0]), "+f"(d[1]), "+f"(d[2]), "+f"(d[3])
        : "r"(a[0]), "r"(a[1]), "r"(a[2]), "r"(a[3]), "r"(b0), "r"(b1));
}

// ---------------------------------------------------------------------------
// fp16 convert: z -> g_Azh; w*1024 -> g_Bwh. Also resets flag counter.
// ---------------------------------------------------------------------------
__global__ void convert_kernel(const float* __restrict__ z,
                               const float* __restrict__ w, int n, int ne) {
    if (blockIdx.x == 0 && threadIdx.x == 0) g_nflag = 0;
    int idx4 = blockIdx.x * blockDim.x + threadIdx.x;
    int nz = n * 64;
    if (idx4 < nz) {
        int r = idx4 >> 6, q = idx4 & 63;
        float4 v = *(const float4*)&z[(size_t)r * D + q * 4];
        union { __half h[4]; uint2 u; } p;
        p.h[0] = __float2half(v.x); p.h[1] = __float2half(v.y);
        p.h[2] = __float2half(v.z); p.h[3] = __float2half(v.w);
        *(uint2*)&g_Azh[(size_t)r * D + q * 4] = p.u;
    } else if (idx4 < nz + ne * 64) {
        int i = idx4 - nz;
        int r = i >> 6, q = i & 63;
        float4 v = *(const float4*)&w[(size_t)r * D + q * 4];
        union { __half h[4]; uint2 u; } p;
        p.h[0] = __float2half(v.x * 1024.0f); p.h[1] = __float2half(v.y * 1024.0f);
        p.h[2] = __float2half(v.z * 1024.0f); p.h[3] = __float2half(v.w * 1024.0f);
        *(uint2*)&g_Bwh[(size_t)r * D + q * 4] = p.u;
    }
}

// ---------------------------------------------------------------------------
// Row sum-of-squares, strictly sequential fp32 (reference order).
// ---------------------------------------------------------------------------
__global__ void sumsq_kernel(const float* __restrict__ x, int which) {
    __shared__ float buf[32][257];
    int r0 = blockIdx.x * 32;
    for (int i = threadIdx.x; i < 32 * 256; i += 256) {
        int r = i >> 8, c = i & 255;
        buf[r][c] = x[(size_t)(r0 + r) * D + c];
    }
    __syncthreads();
    if (threadIdx.x < 32) {
        int r = threadIdx.x;
        float a = 0.0f;
        #pragma unroll 1
        for (int c = 0; c < 256; ++c) {
            float v = buf[r][c];
            a = __fadd_rn(a, __fmul_rn(v, v));
        }
        if (which) g_A[r0 + r] = a;
        else       g_C[r0 + r] = a;
    }
}

// ---------------------------------------------------------------------------
// B slab loader: slab u -> chunk n = u/4, ks = u%4.
// 128 code rows x 64 fp16 (128B), SW128 into ring buffer (u&3).
// ---------------------------------------------------------------------------
__device__ __forceinline__ void load_Bslab(uint32_t sb, int u, int tid) {
    int n = u >> 2, ks = u & 3;
    size_t src0 = (size_t)(n * 128) * 512 + ks * 128;   // row = 512 bytes
    uint32_t dst0 = sb + SM_B + (u & 3) * 16384;
    #pragma unroll
    for (int it = 0; it < 2; ++it) {                 // 1024 chunks / 512 thr
        int i = tid + it * 512;
        int row = i >> 3, sub = i & 7;
        cp_async16(dst0 + SWZ(row * 128 + sub * 16),
                   (const char*)g_Bwh + src0 + (size_t)row * 512 + sub * 16);
    }
}

// ---------------------------------------------------------------------------
// Fused fp16 HMMA GEMM + argmin (+ second-best flagging).
// CTA = 128 tokens, 512 threads (4x4 warps, 32x32 warp tiles). K=256.
// A resident (64KB); B 4-buffer ring. 8 chunks x 4 k-slabs = 32 slabs.
// ---------------------------------------------------------------------------
__global__ void __launch_bounds__(512, 1)
vq_hmma_kernel(int nch) {
    extern __shared__ __align__(1024) char smem[];
    uint32_t sb = smem_u32(smem);
    const int tid = threadIdx.x;
    const int l   = tid & 31, w = tid >> 5;
    const int wm  = w >> 2,  wn = w & 3;
    const int bt0 = blockIdx.x * 128;
    const int nslab = nch * 4;

    // group 0: full A (4 regions x 128 rows x 128B) + B slab 0
    for (int i = tid; i < 4096; i += 512) {
        int r = i >> 10, rem = i & 1023;
        int row = rem >> 3, sub = rem & 7;
        cp_async16(sb + r * 16384 + SWZ(row * 128 + sub * 16),
                   (const char*)g_Azh + (size_t)(bt0 + row) * 512 + r * 128 + sub * 16);
    }
    load_Bslab(sb, 0, tid);
    asm volatile("cp.async.commit_group;" ::: "memory");
    load_Bslab(sb, 1, tid);
    asm volatile("cp.async.commit_group;" ::: "memory");
    load_Bslab(sb, 2, tid);
    asm volatile("cp.async.commit_group;" ::: "memory");

    float Ar[2][2];
    #pragma unroll
    for (int mt = 0; mt < 2; ++mt)
        #pragma unroll
        for (int h = 0; h < 2; ++h)
            Ar[mt][h] = g_A[bt0 + wm * 32 + mt * 16 + h * 8 + (l >> 2)];

    float bd[2][2], bd2[2][2];
    int   bi[2][2];
    #pragma unroll
    for (int mt = 0; mt < 2; ++mt)
        #pragma unroll
        for (int h = 0; h < 2; ++h) {
            bd[mt][h] = __int_as_float(0x7f800000);
            bd2[mt][h] = __int_as_float(0x7f800000);
            bi[mt][h] = 0;
        }

    float acc[2][4][4];
    #pragma unroll
    for (int mt = 0; mt < 2; ++mt)
        #pragma unroll
        for (int nt = 0; nt < 4; ++nt)
            #pragma unroll
            for (int e = 0; e < 4; ++e) acc[mt][nt][e] = 0.0f;

    for (int u = 0; u < nslab; ++u) {
        if (u + 3 < nslab)
            asm volatile("cp.async.wait_group 2;" ::: "memory");
        else
            asm volatile("cp.async.wait_group 0;" ::: "memory");
        __syncthreads();

        if (u + 3 < nslab) {
            load_Bslab(sb, u + 3, tid);
            asm volatile("cp.async.commit_group;" ::: "memory");
        }

        const int ks = u & 3, n = u >> 2;
        const uint32_t abase = sb + ks * 16384;
        const uint32_t bbase = sb + SM_B + (u & 3) * 16384;

        #pragma unroll
        for (int kq = 0; kq < 2; ++kq) {
            uint32_t Bk[4][4];
            #pragma unroll
            for (int nt = 0; nt < 4; ++nt) {
                uint32_t ba = bbase +
                    SWZ((wn * 32 + nt * 8 + (l & 7)) * 128 + kq * 64 + (l >> 3) * 16);
                ldsm4(ba, Bk[nt]);
            }
            uint32_t Aa[2][2][4];
            #pragma unroll
            for (int mt = 0; mt < 2; ++mt)
                #pragma unroll
                for (int kk = 0; kk < 2; ++kk) {
                    uint32_t aa = abase +
                        SWZ((wm * 32 + mt * 16 + (l & 15)) * 128
                            + kq * 64 + kk * 32 + (l >> 4) * 16);
                    ldsm4(aa, Aa[mt][kk]);
                }
            #pragma unroll
            for (int mt = 0; mt < 2; ++mt)
                #pragma unroll
                for (int nt = 0; nt < 4; ++nt) {
                    mma_f16(acc[mt][nt], Aa[mt][0], Bk[nt][0], Bk[nt][1]);
                    mma_f16(acc[mt][nt], Aa[mt][1], Bk[nt][2], Bk[nt][3]);
                }
        }

        if (ks == 3) {
            // chunk epilogue: dist = fl(fl(A - 2d) + C), d = acc/1024 exact
            #pragma unroll
            for (int mt = 0; mt < 2; ++mt)
                #pragma unroll
                for (int h = 0; h < 2; ++h)
                    #pragma unroll
                    for (int nt = 0; nt < 4; ++nt) {
                        int c0 = n * 128 + wn * 32 + nt * 8 + (l & 3) * 2;
                        float C0 = __ldg(&g_C[c0]);
                        float C1 = __ldg(&g_C[c0 + 1]);
                        float q0 = __fadd_rn(__fadd_rn(Ar[mt][h],
                                     acc[mt][nt][h * 2 + 0] * -0.001953125f), C0);
                        if (q0 < bd[mt][h]) { bd2[mt][h] = bd[mt][h]; bd[mt][h] = q0; bi[mt][h] = c0; }
                        else if (q0 < bd2[mt][h]) bd2[mt][h] = q0;
                        float q1 = __fadd_rn(__fadd_rn(Ar[mt][h],
                                     acc[mt][nt][h * 2 + 1] * -0.001953125f), C1);
                        if (q1 < bd[mt][h]) { bd2[mt][h] = bd[mt][h]; bd[mt][h] = q1; bi[mt][h] = c0 + 1; }
                        else if (q1 < bd2[mt][h]) bd2[mt][h] = q1;
                    }
            #pragma unroll
            for (int mt = 0; mt < 2; ++mt)
                #pragma unroll
                for (int nt = 0; nt < 4; ++nt)
                    #pragma unroll
                    for (int e = 0; e < 4; ++e) acc[mt][nt][e] = 0.0f;
        }
    }

    // cross-lane reduce over the 4 lanes sharing each token row
    #pragma unroll
    for (int mt = 0; mt < 2; ++mt)
        #pragma unroll
        for (int h = 0; h < 2; ++h)
            #pragma unroll
            for (int off = 1; off <= 2; off <<= 1) {
                float od  = __shfl_xor_sync(0xffffffffu, bd[mt][h], off);
                int   oi  = __shfl_xor_sync(0xffffffffu, bi[mt][h], off);
                float od2 = __shfl_xor_sync(0xffffffffu, bd2[mt][h], off);
                float mx  = fmaxf(bd[mt][h], od);
                bd2[mt][h] = fminf(fminf(bd2[mt][h], od2), mx);
                if (od < bd[mt][h] || (od == bd[mt][h] && oi < bi[mt][h])) {
                    bd[mt][h] = od; bi[mt][h] = oi;
                }
            }

    __syncthreads();                     // B ring dead; reuse for staging
    float* stD  = (float*)(smem + SM_B);
    int*   stI  = (int*)(smem + SM_B + 2048);
    float* stD2 = (float*)(smem + SM_B + 4096);
    if ((l & 3) == 0) {
        #pragma unroll
        for (int mt = 0; mt < 2; ++mt)
            #pragma unroll
            for (int h = 0; h < 2; ++h) {
                int t = wm * 32 + mt * 16 + h * 8 + (l >> 2);
                stD[t * 4 + wn]  = bd[mt][h];
                stI[t * 4 + wn]  = bi[mt][h];
                stD2[t * 4 + wn] = bd2[mt][h];
            }
    }
    __syncthreads();
    if (tid < 128) {
        float db = stD[tid * 4];
        int   ib = stI[tid * 4];
        float s2 = stD2[tid * 4];
        #pragma unroll
        for (int m = 1; m < 4; ++m) {
            float d = stD[tid * 4 + m];
            int   i = stI[tid * 4 + m];
            float d2 = stD2[tid * 4 + m];
            s2 = fminf(s2, d2);
            if (d < db || (d == db && i < ib)) { s2 = fminf(s2, db); db = d; ib = i; }
            else s2 = fminf(s2, d);
        }
        g_idx[bt0 + tid] = ib;
        if (s2 - db < TAU) {                      // ambiguous: exact re-check
            int pos = atomicAdd(&g_nflag, 1);
            g_flag[pos] = bt0 + tid;
        }
    }
}

// ---------------------------------------------------------------------------
// Batched exact fp32 refinement. Block = up to 32 flagged tokens vs all
// 1024 codes. Per-dot arithmetic is the sequential k-ascending fp32 FMA
// chain + identical epilogue rounding to the proven round-1 kernel; winner
// by lexicographic (dist, idx) min == first-min tie-break.
// WT reads are SCALAR (stride-33 array is not float4-aligned — R10 crash);
// all lanes of a warp read the same word, so these are smem broadcasts.
// ---------------------------------------------------------------------------
#define REF_SMEM ((32 * 257 + 256 * 33) * 4)
__global__ void __launch_bounds__(256, 1)
vq_refine_kernel(const float* __restrict__ z, const float* __restrict__ w) {
    extern __shared__ __align__(16) float sref[];
    float* zb = sref;                  // 32 tokens x stride 257
    float* WT = zb + 32 * 257;         // chunk transposed [k][c], stride 33
    __shared__ float sA[32];
    __shared__ int   tk[32];
    __shared__ float stD[32 * 8];
    __shared__ int   stI[32 * 8];

    const int tid = threadIdx.x;
    const int nf = g_nflag;
    const int base = blockIdx.x * 32;
    if (base >= nf) return;
    const int cnt = min(32, nf - base);

    if (tid < 32) {
        int t = (tid < cnt) ? g_flag[base + tid] : g_flag[base];
        tk[tid] = t;
        sA[tid] = g_A[t];
    }
    __syncthreads();
    for (int i = tid; i < 32 * 64; i += 256) {       // 32 rows x 64 float4
        int tt = i >> 6, q = (i & 63) * 4;
        float4 v = *(const float4*)&z[(size_t)tk[tt] * D + q];
        float* d = zb + tt * 257 + q;
        d[0] = v.x; d[1] = v.y; d[2] = v.z; d[3] = v.w;
    }

    const int tt  = tid & 31;          // token (whole warp same grp)
    const int grp = tid >> 5;          // code subgroup 0..7
    const float A = sA[tt];
    float bdl = __int_as_float(0x7f800000);
    int   bil = 0x7fffffff;

    for (int ch = 0; ch < 32; ++ch) {                // 32 codes per chunk
        __syncthreads();
        for (int i = tid; i < 32 * 64; i += 256) {   // stage transposed
            int row = i >> 6, q = (i & 63) * 4;
            float4 v = *(const float4*)&w[(size_t)(ch * 32 + row) * D + q];
            WT[(q + 0) * 33 + row] = v.x;
            WT[(q + 1) * 33 + row] = v.y;
            WT[(q + 2) * 33 + row] = v.z;
            WT[(q + 3) * 33 + row] = v.w;
        }
        __syncthreads();
        float a0 = 0.0f, a1 = 0.0f, a2 = 0.0f, a3 = 0.0f;
        const float* zr = zb + tt * 257;
        const float* wr = WT + grp * 4;
        #pragma unroll 4
        for (int k = 0; k < 256; ++k) {              // 4 parallel exact chains
            float zv = zr[k];
            const float* wk = wr + k * 33;           // broadcast scalar LDS
            a0 = fmaf(zv, wk[0], a0);
            a1 = fmaf(zv, wk[1], a1);
            a2 = fmaf(zv, wk[2], a2);
            a3 = fmaf(zv, wk[3], a3);
        }
        int c = ch * 32 + grp * 4;                   // ascending per thread
        float q0 = __fadd_rn(__fadd_rn(A, -2.0f * a0), __ldg(&g_C[c + 0]));
        if (q0 < bdl) { bdl = q0; bil = c + 0; }
        float q1 = __fadd_rn(__fadd_rn(A, -2.0f * a1), __ldg(&g_C[c + 1]));
        if (q1 < bdl) { bdl = q1; bil = c + 1; }
        float q2 = __fadd_rn(__fadd_rn(A, -2.0f * a2), __ldg(&g_C[c + 2]));
        if (q2 < bdl) { bdl = q2; bil = c + 2; }
        float q3 = __fadd_rn(__fadd_rn(A, -2.0f * a3), __ldg(&g_C[c + 3]));
        if (q3 < bdl) { bdl = q3; bil = c + 3; }
    }

    stD[tt * 8 + grp] = bdl;
    stI[tt * 8 + grp] = bil;
    __syncthreads();
    if (tid < 32 && tid < cnt) {
        float b = stD[tid * 8]; int v = stI[tid * 8];
        #pragma unroll
        for (int m = 1; m < 8; ++m) {
            float d = stD[tid * 8 + m];
            int   i = stI[tid * 8 + m];
            if (d < b || (d == b && i < v)) { b = d; v = i; }
        }
        g_idx[tk[tid]] = v;
    }
}

// ---------------------------------------------------------------------------
// Output: warp per token. z_q_st = fl(z + fl(zq-z)); loss = fl(m + fl(.25m))
// ---------------------------------------------------------------------------
__global__ void vq_out_kernel(const float* __restrict__ z, const float* __restrict__ w,
                              float* __restrict__ out_zq, float* __restrict__ out_loss,
                              float* __restrict__ out_idx) {
    int warp = threadIdx.x >> 5, lane = threadIdx.x & 31;
    int t = blockIdx.x * 8 + warp;
    int j = g_idx[t];
    const float4* zp = (const float4*)(z + (size_t)t * D);
    const float4* wp = (const float4*)(w + (size_t)j * D);
    float4* op = (float4*)(out_zq + (size_t)t * D);
    float sq = 0.0f;
    #pragma unroll
    for (int i = 0; i < 2; ++i) {
        float4 zv = zp[lane + 32 * i];
        float4 wv = wp[lane + 32 * i];
        float4 o;
        float d;
        d = __fadd_rn(wv.x, -zv.x); o.x = __fadd_rn(zv.x, d); sq = __fadd_rn(sq, __fmul_rn(d, d));
        d = __fadd_rn(wv.y, -zv.y); o.y = __fadd_rn(zv.y, d); sq = __fadd_rn(sq, __fmul_rn(d, d));
        d = __fadd_rn(wv.z, -zv.z); o.z = __fadd_rn(zv.z, d); sq = __fadd_rn(sq, __fmul_rn(d, d));
        d = __fadd_rn(wv.w, -zv.w); o.w = __fadd_rn(zv.w, d); sq = __fadd_rn(sq, __fmul_rn(d, d));
        op[lane + 32 * i] = o;
    }
    #pragma unroll
    for (int o = 16; o > 0; o >>= 1) sq += __shfl_xor_sync(0xffffffffu, sq, o);
    if (lane == 0) {
        float m = sq * (1.0f / 256.0f);
        out_loss[t] = __fadd_rn(m, __fmul_rn(0.25f, m));
        out_idx[t]  = (float)j;
    }
}

// ---------------------------------------------------------------------------
extern "C" void kernel_launch(void* const* d_in, const int* in_sizes, int n_in,
                              void* d_out, int out_size) {
    const float* z = (const float*)d_in[0];
    const float* w = (const float*)d_in[1];
    const int n  = in_sizes[0] / D;   // 65536
    const int ne = in_sizes[1] / D;   // 1024
    float* out      = (float*)d_out;
    float* out_loss = out + (size_t)n * D;
    float* out_idx  = out_loss + n;

    convert_kernel<<<(n * 64 + ne * 64 + 255) / 256, 256>>>(z, w, n, ne);
    sumsq_kernel<<<n / 32, 256>>>(z, 1);
    sumsq_kernel<<<ne / 32, 256>>>(w, 0);

    cudaFuncSetAttribute(vq_hmma_kernel,
                         cudaFuncAttributeMaxDynamicSharedMemorySize, SM_TOT);
    vq_hmma_kernel<<<n / 128, 512, SM_TOT>>>(ne / 128);   // launch #4: profiled

    cudaFuncSetAttribute(vq_refine_kernel,
                         cudaFuncAttributeMaxDynamicSharedMemorySize, REF_SMEM);
    vq_refine_kernel<<<2048, 256, REF_SMEM>>>(z, w);

    vq_out_kernel<<<n / 8, 256>>>(z, w, out, out_loss, out_idx);
}

// round 12
// speedup vs baseline: 3.6885x; 1.9019x over previous
#include <cuda_runtime.h>
#include <cuda_fp16.h>
#include <stdint.h>
#include <math.h>

// VectorQuantizer: z [65536,256] f32, W [1024,256] f32.
// dist = ||z||^2 - 2 z.W^T + ||w||^2 ; idx = argmin (first-min tie-break)
// out (f32): z_q_st [N*256] | loss [N] | idx [N]
//
// fp16 HMMA (K=256, w scaled x1024) computes ALL dists, writes them to g_D,
// and tracks per-token best/second-best. Rigorous worst-case fp16 dist error
// <= 3.1e-4 per dot => 6.2e-4 on dist; TAU = 7e-4 >= 2*err. Tokens with
// second-best gap < TAU are re-resolved: candidates = {c: d_hmma < bd+TAU}
// (provable superset of true argmin), each recomputed with the exact
// sequential fp32 chain of the proven round-1 kernel; first-min tie-break.

#define D    256
#define NTOK 65536
#define NE   1024
#define TAU  7e-4f

__device__ float g_A[NTOK];
__device__ float g_C[NE];
__device__ float g_bd[NTOK];
__device__ int   g_idx[NTOK];
__device__ int   g_nflag;
__device__ int   g_flag[NTOK];
__device__ __align__(256) float  g_D[(size_t)NTOK * NE];   // hmma dists
__device__ __align__(256) __half g_Azh[(size_t)NTOK * D];
__device__ __align__(256) __half g_Bwh[(size_t)NE * D];

// smem: A resident 4 regions x 16KB (SW128) + B ring 4 x 16KB
#define SM_B   65536
#define SM_TOT 131072
#define SWZ(o) ((o) ^ (((o) >> 3) & 0x70))

__device__ __forceinline__ uint32_t smem_u32(const void* p) {
    uint32_t a;
    asm("{ .reg .u64 t; cvta.to.shared.u64 t, %1; cvt.u32.u64 %0, t; }" : "=r"(a) : "l"(p));
    return a;
}
__device__ __forceinline__ void cp_async16(uint32_t dst, const void* src) {
    asm volatile("cp.async.cg.shared.global [%0], [%1], 16;" :: "r"(dst), "l"(src) : "memory");
}
__device__ __forceinline__ void ldsm4(uint32_t a, uint32_t r[4]) {
    asm volatile("ldmatrix.sync.aligned.m8n8.x4.shared.b16 {%0,%1,%2,%3}, [%4];"
                 : "=r"(r[0]), "=r"(r[1]), "=r"(r[2]), "=r"(r[3]) : "r"(a));
}
__device__ __forceinline__ void mma_f16(float d[4], const uint32_t a[4],
                                        uint32_t b0, uint32_t b1) {
    asm volatile(
        "mma.sync.aligned.m16n8k16.row.col.f32.f16.f16.f32 "
        "{%0,%1,%2,%3}, {%4,%5,%6,%7}, {%8,%9}, {%0,%1,%2,%3};"
        : "+f"(d[0]), "+f"(d[1]), "+f"(d[2]), "+f"(d[3])
        : "r"(a[0]), "r"(a[1]), "r"(a[2]), "r"(a[3]), "r"(b0), "r"(b1));
}

// ---------------------------------------------------------------------------
// fp16 convert: z -> g_Azh; w*1024 -> g_Bwh. Also resets flag counter.
// ---------------------------------------------------------------------------
__global__ void convert_kernel(const float* __restrict__ z,
                               const float* __restrict__ w, int n, int ne) {
    if (blockIdx.x == 0 && threadIdx.x == 0) g_nflag = 0;
    int idx4 = blockIdx.x * blockDim.x + threadIdx.x;
    int nz = n * 64;
    if (idx4 < nz) {
        int r = idx4 >> 6, q = idx4 & 63;
        float4 v = *(const float4*)&z[(size_t)r * D + q * 4];
        union { __half h[4]; uint2 u; } p;
        p.h[0] = __float2half(v.x); p.h[1] = __float2half(v.y);
        p.h[2] = __float2half(v.z); p.h[3] = __float2half(v.w);
        *(uint2*)&g_Azh[(size_t)r * D + q * 4] = p.u;
    } else if (idx4 < nz + ne * 64) {
        int i = idx4 - nz;
        int r = i >> 6, q = i & 63;
        float4 v = *(const float4*)&w[(size_t)r * D + q * 4];
        union { __half h[4]; uint2 u; } p;
        p.h[0] = __float2half(v.x * 1024.0f); p.h[1] = __float2half(v.y * 1024.0f);
        p.h[2] = __float2half(v.z * 1024.0f); p.h[3] = __float2half(v.w * 1024.0f);
        *(uint2*)&g_Bwh[(size_t)r * D + q * 4] = p.u;
    }
}

// ---------------------------------------------------------------------------
// Row sum-of-squares, strictly sequential fp32 (reference order).
// ---------------------------------------------------------------------------
__global__ void sumsq_kernel(const float* __restrict__ x, int which) {
    __shared__ float buf[32][257];
    int r0 = blockIdx.x * 32;
    for (int i = threadIdx.x; i < 32 * 256; i += 256) {
        int r = i >> 8, c = i & 255;
        buf[r][c] = x[(size_t)(r0 + r) * D + c];
    }
    __syncthreads();
    if (threadIdx.x < 32) {
        int r = threadIdx.x;
        float a = 0.0f;
        #pragma unroll 1
        for (int c = 0; c < 256; ++c) {
            float v = buf[r][c];
            a = __fadd_rn(a, __fmul_rn(v, v));
        }
        if (which) g_A[r0 + r] = a;
        else       g_C[r0 + r] = a;
    }
}

// ---------------------------------------------------------------------------
// B slab loader: slab u -> chunk n = u/4, ks = u%4.
// 128 code rows x 64 fp16 (128B), SW128 into ring buffer (u&3).
// ---------------------------------------------------------------------------
__device__ __forceinline__ void load_Bslab(uint32_t sb, int u, int tid) {
    int n = u >> 2, ks = u & 3;
    size_t src0 = (size_t)(n * 128) * 512 + ks * 128;   // row = 512 bytes
    uint32_t dst0 = sb + SM_B + (u & 3) * 16384;
    #pragma unroll
    for (int it = 0; it < 2; ++it) {                 // 1024 chunks / 512 thr
        int i = tid + it * 512;
        int row = i >> 3, sub = i & 7;
        cp_async16(dst0 + SWZ(row * 128 + sub * 16),
                   (const char*)g_Bwh + src0 + (size_t)row * 512 + sub * 16);
    }
}

// ---------------------------------------------------------------------------
// Fused fp16 HMMA GEMM + argmin (+ dist-matrix write + 2nd-best flagging).
// CTA = 128 tokens, 512 threads (4x4 warps, 32x32 warp tiles). K=256.
// ---------------------------------------------------------------------------
__global__ void __launch_bounds__(512, 1)
vq_hmma_kernel(int nch) {
    extern __shared__ __align__(1024) char smem[];
    uint32_t sb = smem_u32(smem);
    const int tid = threadIdx.x;
    const int l   = tid & 31, w = tid >> 5;
    const int wm  = w >> 2,  wn = w & 3;
    const int bt0 = blockIdx.x * 128;
    const int nslab = nch * 4;

    // group 0: full A (4 regions x 128 rows x 128B) + B slab 0
    for (int i = tid; i < 4096; i += 512) {
        int r = i >> 10, rem = i & 1023;
        int row = rem >> 3, sub = rem & 7;
        cp_async16(sb + r * 16384 + SWZ(row * 128 + sub * 16),
                   (const char*)g_Azh + (size_t)(bt0 + row) * 512 + r * 128 + sub * 16);
    }
    load_Bslab(sb, 0, tid);
    asm volatile("cp.async.commit_group;" ::: "memory");
    load_Bslab(sb, 1, tid);
    asm volatile("cp.async.commit_group;" ::: "memory");
    load_Bslab(sb, 2, tid);
    asm volatile("cp.async.commit_group;" ::: "memory");

    float Ar[2][2];
    #pragma unroll
    for (int mt = 0; mt < 2; ++mt)
        #pragma unroll
        for (int h = 0; h < 2; ++h)
            Ar[mt][h] = g_A[bt0 + wm * 32 + mt * 16 + h * 8 + (l >> 2)];

    float bd[2][2], bd2[2][2];
    int   bi[2][2];
    #pragma unroll
    for (int mt = 0; mt < 2; ++mt)
        #pragma unroll
        for (int h = 0; h < 2; ++h) {
            bd[mt][h] = __int_as_float(0x7f800000);
            bd2[mt][h] = __int_as_float(0x7f800000);
            bi[mt][h] = 0;
        }

    float acc[2][4][4];
    #pragma unroll
    for (int mt = 0; mt < 2; ++mt)
        #pragma unroll
        for (int nt = 0; nt < 4; ++nt)
            #pragma unroll
            for (int e = 0; e < 4; ++e) acc[mt][nt][e] = 0.0f;

    for (int u = 0; u < nslab; ++u) {
        if (u + 3 < nslab)
            asm volatile("cp.async.wait_group 2;" ::: "memory");
        else
            asm volatile("cp.async.wait_group 0;" ::: "memory");
        __syncthreads();

        if (u + 3 < nslab) {
            load_Bslab(sb, u + 3, tid);
            asm volatile("cp.async.commit_group;" ::: "memory");
        }

        const int ks = u & 3, n = u >> 2;
        const uint32_t abase = sb + ks * 16384;
        const uint32_t bbase = sb + SM_B + (u & 3) * 16384;

        #pragma unroll
        for (int kq = 0; kq < 2; ++kq) {
            uint32_t Bk[4][4];
            #pragma unroll
            for (int nt = 0; nt < 4; ++nt) {
                uint32_t ba = bbase +
                    SWZ((wn * 32 + nt * 8 + (l & 7)) * 128 + kq * 64 + (l >> 3) * 16);
                ldsm4(ba, Bk[nt]);
            }
            uint32_t Aa[2][2][4];
            #pragma unroll
            for (int mt = 0; mt < 2; ++mt)
                #pragma unroll
                for (int kk = 0; kk < 2; ++kk) {
                    uint32_t aa = abase +
                        SWZ((wm * 32 + mt * 16 + (l & 15)) * 128
                            + kq * 64 + kk * 32 + (l >> 4) * 16);
                    ldsm4(aa, Aa[mt][kk]);
                }
            #pragma unroll
            for (int mt = 0; mt < 2; ++mt)
                #pragma unroll
                for (int nt = 0; nt < 4; ++nt) {
                    mma_f16(acc[mt][nt], Aa[mt][0], Bk[nt][0], Bk[nt][1]);
                    mma_f16(acc[mt][nt], Aa[mt][1], Bk[nt][2], Bk[nt][3]);
                }
        }

        if (ks == 3) {
            // chunk epilogue: dist = fl(fl(A - 2d) + C); write to g_D;
            // fold first-min + second-best
            #pragma unroll
            for (int mt = 0; mt < 2; ++mt)
                #pragma unroll
                for (int h = 0; h < 2; ++h) {
                    const int trow = wm * 32 + mt * 16 + h * 8 + (l >> 2);
                    #pragma unroll
                    for (int nt = 0; nt < 4; ++nt) {
                        int c0 = n * 128 + wn * 32 + nt * 8 + (l & 3) * 2;
                        float C0 = __ldg(&g_C[c0]);
                        float C1 = __ldg(&g_C[c0 + 1]);
                        float q0 = __fadd_rn(__fadd_rn(Ar[mt][h],
                                     acc[mt][nt][h * 2 + 0] * -0.001953125f), C0);
                        float q1 = __fadd_rn(__fadd_rn(Ar[mt][h],
                                     acc[mt][nt][h * 2 + 1] * -0.001953125f), C1);
                        float2 qv; qv.x = q0; qv.y = q1;
                        *(float2*)&g_D[(size_t)(bt0 + trow) * NE + c0] = qv;
                        if (q0 < bd[mt][h]) { bd2[mt][h] = bd[mt][h]; bd[mt][h] = q0; bi[mt][h] = c0; }
                        else if (q0 < bd2[mt][h]) bd2[mt][h] = q0;
                        if (q1 < bd[mt][h]) { bd2[mt][h] = bd[mt][h]; bd[mt][h] = q1; bi[mt][h] = c0 + 1; }
                        else if (q1 < bd2[mt][h]) bd2[mt][h] = q1;
                    }
                }
            #pragma unroll
            for (int mt = 0; mt < 2; ++mt)
                #pragma unroll
                for (int nt = 0; nt < 4; ++nt)
                    #pragma unroll
                    for (int e = 0; e < 4; ++e) acc[mt][nt][e] = 0.0f;
        }
    }

    // cross-lane reduce over the 4 lanes sharing each token row
    #pragma unroll
    for (int mt = 0; mt < 2; ++mt)
        #pragma unroll
        for (int h = 0; h < 2; ++h)
            #pragma unroll
            for (int off = 1; off <= 2; off <<= 1) {
                float od  = __shfl_xor_sync(0xffffffffu, bd[mt][h], off);
                int   oi  = __shfl_xor_sync(0xffffffffu, bi[mt][h], off);
                float od2 = __shfl_xor_sync(0xffffffffu, bd2[mt][h], off);
                float mx  = fmaxf(bd[mt][h], od);
                bd2[mt][h] = fminf(fminf(bd2[mt][h], od2), mx);
                if (od < bd[mt][h] || (od == bd[mt][h] && oi < bi[mt][h])) {
                    bd[mt][h] = od; bi[mt][h] = oi;
                }
            }

    __syncthreads();                     // B ring dead; reuse for staging
    float* stD  = (float*)(smem + SM_B);
    int*   stI  = (int*)(smem + SM_B + 2048);
    float* stD2 = (float*)(smem + SM_B + 4096);
    if ((l & 3) == 0) {
        #pragma unroll
        for (int mt = 0; mt < 2; ++mt)
            #pragma unroll
            for (int h = 0; h < 2; ++h) {
                int t = wm * 32 + mt * 16 + h * 8 + (l >> 2);
                stD[t * 4 + wn]  = bd[mt][h];
                stI[t * 4 + wn]  = bi[mt][h];
                stD2[t * 4 + wn] = bd2[mt][h];
            }
    }
    __syncthreads();
    if (tid < 128) {
        float db = stD[tid * 4];
        int   ib = stI[tid * 4];
        float s2 = stD2[tid * 4];
        #pragma unroll
        for (int m = 1; m < 4; ++m) {
            float d = stD[tid * 4 + m];
            int   i = stI[tid * 4 + m];
            float d2 = stD2[tid * 4 + m];
            s2 = fminf(s2, d2);
            if (d < db || (d == db && i < ib)) { s2 = fminf(s2, db); db = d; ib = i; }
            else s2 = fminf(s2, d);
        }
        g_idx[bt0 + tid] = ib;
        g_bd[bt0 + tid]  = db;
        if (s2 - db < TAU) {                      // ambiguous: exact re-check
            int pos = atomicAdd(&g_nflag, 1);
            g_flag[pos] = bt0 + tid;
        }
    }
}

// ---------------------------------------------------------------------------
// Candidate-pruned exact refinement. Warp per flagged token: scan the
// token's 1024 hmma dists, candidates = {c : d < bd + TAU} (superset of
// the true argmin since TAU >= 2*err_max). Each candidate recomputed with
// the exact sequential k-ascending fp32 FMA chain + identical epilogue
// rounding of the proven round-1 kernel; lexicographic (dist, idx) min.
// ---------------------------------------------------------------------------
__global__ void __launch_bounds__(256, 1)
vq_refine_kernel(const float* __restrict__ z, const float* __restrict__ w) {
    __shared__ float zs[8][256];
    const int lane = threadIdx.x & 31, wl = threadIdx.x >> 5;
    const int gw = blockIdx.x * 8 + wl;
    const int nwarp = gridDim.x * 8;
    const int nf = g_nflag;

    for (int it = gw; it < nf; it += nwarp) {
        const int t = g_flag[it];
        float* zr = zs[wl];
        #pragma unroll
        for (int q = 0; q < 2; ++q) {             // coalesced float4 loads
            float4 v = *(const float4*)&z[(size_t)t * D + (lane + q * 32) * 4];
            zr[(lane + q * 32) * 4 + 0] = v.x;
            zr[(lane + q * 32) * 4 + 1] = v.y;
            zr[(lane + q * 32) * 4 + 2] = v.z;
            zr[(lane + q * 32) * 4 + 3] = v.w;
        }
        __syncwarp();
        const float thr = g_bd[t] + TAU;
        const float A   = g_A[t];
        const float* drow = g_D + (size_t)t * NE;

        float bestd = __int_as_float(0x7f800000);
        int   besti = 0x7fffffff;
        for (int c0 = 0; c0 < NE; c0 += 32) {
            float dv = drow[c0 + lane];
            unsigned m = __ballot_sync(0xffffffffu, dv < thr);
            int nc = __popc(m);
            if (nc == 0) continue;
            int myc = -1;
            if (lane < nc) {                       // lane takes its rank-th bit
                unsigned mm = m;
                for (int r = 0; r < lane; ++r) mm &= mm - 1;
                myc = c0 + __ffs(mm) - 1;
            }
            float dist = __int_as_float(0x7f800000);
            if (myc >= 0) {
                float acc = 0.0f;
                const float* wr = w + (size_t)myc * D;
                #pragma unroll 8
                for (int k = 0; k < 256; ++k)      // exact sequential chain
                    acc = fmaf(zr[k], __ldg(&wr[k]), acc);
                dist = __fadd_rn(__fadd_rn(A, -2.0f * acc), __ldg(&g_C[myc]));
            }
            if (myc >= 0 && (dist < bestd || (dist == bestd && myc < besti))) {
                bestd = dist; besti = myc;
            }
        }
        #pragma unroll
        for (int off = 16; off > 0; off >>= 1) {
            float od = __shfl_xor_sync(0xffffffffu, bestd, off);
            int   oi = __shfl_xor_sync(0xffffffffu, besti, off);
            if (od < bestd || (od == bestd && oi < besti)) { bestd = od; besti = oi; }
        }
        if (lane == 0) g_idx[t] = besti;
        __syncwarp();
    }
}

// ---------------------------------------------------------------------------
// Output: warp per token. z_q_st = fl(z + fl(zq-z)); loss = fl(m + fl(.25m))
// ---------------------------------------------------------------------------
__global__ void vq_out_kernel(const float* __restrict__ z, const float* __restrict__ w,
                              float* __restrict__ out_zq, float* __restrict__ out_loss,
                              float* __restrict__ out_idx) {
    int warp = threadIdx.x >> 5, lane = threadIdx.x & 31;
    int t = blockIdx.x * 8 + warp;
    int j = g_idx[t];
    const float4* zp = (const float4*)(z + (size_t)t * D);
    const float4* wp = (const float4*)(w + (size_t)j * D);
    float4* op = (float4*)(out_zq + (size_t)t * D);
    float sq = 0.0f;
    #pragma unroll
    for (int i = 0; i < 2; ++i) {
        float4 zv = zp[lane + 32 * i];
        float4 wv = wp[lane + 32 * i];
        float4 o;
        float d;
        d = __fadd_rn(wv.x, -zv.x); o.x = __fadd_rn(zv.x, d); sq = __fadd_rn(sq, __fmul_rn(d, d));
        d = __fadd_rn(wv.y, -zv.y); o.y = __fadd_rn(zv.y, d); sq = __fadd_rn(sq, __fmul_rn(d, d));
        d = __fadd_rn(wv.z, -zv.z); o.z = __fadd_rn(zv.z, d); sq = __fadd_rn(sq, __fmul_rn(d, d));
        d = __fadd_rn(wv.w, -zv.w); o.w = __fadd_rn(zv.w, d); sq = __fadd_rn(sq, __fmul_rn(d, d));
        op[lane + 32 * i] = o;
    }
    #pragma unroll
    for (int o = 16; o > 0; o >>= 1) sq += __shfl_xor_sync(0xffffffffu, sq, o);
    if (lane == 0) {
        float m = sq * (1.0f / 256.0f);
        out_loss[t] = __fadd_rn(m, __fmul_rn(0.25f, m));
        out_idx[t]  = (float)j;
    }
}

// ---------------------------------------------------------------------------
extern "C" void kernel_launch(void* const* d_in, const int* in_sizes, int n_in,
                              void* d_out, int out_size) {
    const float* z = (const float*)d_in[0];
    const float* w = (const float*)d_in[1];
    const int n  = in_sizes[0] / D;   // 65536
    const int ne = in_sizes[1] / D;   // 1024
    float* out      = (float*)d_out;
    float* out_loss = out + (size_t)n * D;
    float* out_idx  = out_loss + n;

    convert_kernel<<<(n * 64 + ne * 64 + 255) / 256, 256>>>(z, w, n, ne);
    sumsq_kernel<<<n / 32, 256>>>(z, 1);
    sumsq_kernel<<<ne / 32, 256>>>(w, 0);

    cudaFuncSetAttribute(vq_hmma_kernel,
                         cudaFuncAttributeMaxDynamicSharedMemorySize, SM_TOT);
    vq_hmma_kernel<<<n / 128, 512, SM_TOT>>>(ne / 128);   // launch #4: profiled

    vq_refine_kernel<<<1024, 256>>>(z, w);

    vq_out_kernel<<<n / 8, 256>>>(z, w, out, out_loss, out_idx);
}

// round 13
// speedup vs baseline: 4.2704x; 1.1578x over previous
#include <cuda_runtime.h>
#include <cuda_fp16.h>
#include <stdint.h>
#include <math.h>

// VectorQuantizer: z [65536,256] f32, W [1024,256] f32.
// dist = ||z||^2 - 2 z.W^T + ||w||^2 ; idx = argmin (first-min tie-break)
// out (f32): z_q_st [N*256] | loss [N] | idx [N]
//
// fp16 HMMA (K=256, w scaled x1024) computes ALL dists, writes them to g_D,
// and tracks per-token best/second-best. Worst-case fp16 dist error
// <= 3.1e-4 per dot => 6.2e-4 on dist; TAU = 7e-4 >= 2*err. Tokens with
// second-best gap < TAU are re-resolved: candidates = {c: d_hmma < bd+TAU}
// (provable superset of true argmin), each recomputed with the exact
// sequential fp32 chain of the proven round-1 kernel; first-min tie-break.
// CTA = 64 tokens x 256 threads, 2 CTAs/SM (barrier overlap).

#define D    256
#define NTOK 65536
#define NE   1024
#define TAU  7e-4f

__device__ float g_A[NTOK];
__device__ float g_C[NE];
__device__ float g_bd[NTOK];
__device__ int   g_idx[NTOK];
__device__ int   g_nflag;
__device__ int   g_flag[NTOK];
__device__ __align__(256) float  g_D[(size_t)NTOK * NE];   // hmma dists
__device__ __align__(256) __half g_Azh[(size_t)NTOK * D];
__device__ __align__(256) __half g_Bwh[(size_t)NE * D];

// smem: A resident 4 slabs x 8KB (SW128) + B ring 4 x 16KB
#define SM_B   32768
#define SM_TOT 98304
#define SWZ(o) ((o) ^ (((o) >> 3) & 0x70))

__device__ __forceinline__ uint32_t smem_u32(const void* p) {
    uint32_t a;
    asm("{ .reg .u64 t; cvta.to.shared.u64 t, %1; cvt.u32.u64 %0, t; }" : "=r"(a) : "l"(p));
    return a;
}
__device__ __forceinline__ void cp_async16(uint32_t dst, const void* src) {
    asm volatile("cp.async.cg.shared.global [%0], [%1], 16;" :: "r"(dst), "l"(src) : "memory");
}
__device__ __forceinline__ void ldsm4(uint32_t a, uint32_t r[4]) {
    asm volatile("ldmatrix.sync.aligned.m8n8.x4.shared.b16 {%0,%1,%2,%3}, [%4];"
                 : "=r"(r[0]), "=r"(r[1]), "=r"(r[2]), "=r"(r[3]) : "r"(a));
}
__device__ __forceinline__ void mma_f16(float d[4], const uint32_t a[4],
                                        uint32_t b0, uint32_t b1) {
    asm volatile(
        "mma.sync.aligned.m16n8k16.row.col.f32.f16.f16.f32 "
        "{%0,%1,%2,%3}, {%4,%5,%6,%7}, {%8,%9}, {%0,%1,%2,%3};"
        : "+f"(d[0]), "+f"(d[1]), "+f"(d[2]), "+f"(d[3])
        : "r"(a[0]), "r"(a[1]), "r"(a[2]), "r"(a[3]), "r"(b0), "r"(b1));
}

// ---------------------------------------------------------------------------
// Fused prep: per 32 rows, (a) strictly-sequential fp32 sum-of-squares
// (reference order), (b) fp16 conversion (w scaled x1024). which=1 -> z.
// ---------------------------------------------------------------------------
__global__ void prep_kernel(const float* __restrict__ x, int which) {
    __shared__ float buf[32][257];
    if (which == 0 && blockIdx.x == 0 && threadIdx.x == 0) g_nflag = 0;
    int r0 = blockIdx.x * 32;
    const float scl = which ? 1.0f : 1024.0f;
    __half* dst = which ? g_Azh : g_Bwh;
    for (int i = threadIdx.x; i < 32 * 64; i += 256) {   // 32 rows x 64 float4
        int r = i >> 6, q = (i & 63) * 4;
        float4 v = *(const float4*)&x[(size_t)(r0 + r) * D + q];
        float* b = &buf[r][q];
        b[0] = v.x; b[1] = v.y; b[2] = v.z; b[3] = v.w;
        union { __half h[4]; uint2 u; } p;
        p.h[0] = __float2half(v.x * scl); p.h[1] = __float2half(v.y * scl);
        p.h[2] = __float2half(v.z * scl); p.h[3] = __float2half(v.w * scl);
        *(uint2*)&dst[(size_t)(r0 + r) * D + q] = p.u;
    }
    __syncthreads();
    if (threadIdx.x < 32) {
        int r = threadIdx.x;
        float a = 0.0f;
        #pragma unroll 1
        for (int c = 0; c < 256; ++c) {
            float v = buf[r][c];
            a = __fadd_rn(a, __fmul_rn(v, v));
        }
        if (which) g_A[r0 + r] = a;
        else       g_C[r0 + r] = a;
    }
}

// ---------------------------------------------------------------------------
// B slab loader: slab u -> chunk n = u/4, ks = u%4.
// 128 code rows x 64 fp16 (128B), SW128 into ring buffer (u&3).
// ---------------------------------------------------------------------------
__device__ __forceinline__ void load_Bslab(uint32_t sb, int u, int tid) {
    int n = u >> 2, ks = u & 3;
    size_t src0 = (size_t)(n * 128) * 512 + ks * 128;   // row = 512 bytes
    uint32_t dst0 = sb + SM_B + (u & 3) * 16384;
    #pragma unroll
    for (int it = 0; it < 4; ++it) {                 // 1024 chunks / 256 thr
        int i = tid + it * 256;
        int row = i >> 3, sub = i & 7;
        cp_async16(dst0 + SWZ(row * 128 + sub * 16),
                   (const char*)g_Bwh + src0 + (size_t)row * 512 + sub * 16);
    }
}

// ---------------------------------------------------------------------------
// Fused fp16 HMMA GEMM + argmin (+ dist-matrix write + 2nd-best flagging).
// CTA = 64 tokens, 256 threads (2x4 warps, 32x32 warp tiles). K=256.
// 2 CTAs/SM: 96KB smem + 128 regs/thread each.
// ---------------------------------------------------------------------------
__global__ void __launch_bounds__(256, 2)
vq_hmma_kernel(int nch) {
    extern __shared__ __align__(1024) char smem[];
    uint32_t sb = smem_u32(smem);
    const int tid = threadIdx.x;
    const int l   = tid & 31, w = tid >> 5;
    const int wm  = w >> 2,  wn = w & 3;
    const int bt0 = blockIdx.x * 64;
    const int nslab = nch * 4;

    // group 0: full A (4 slabs x 64 rows x 128B = 32KB) + B slab 0
    #pragma unroll
    for (int it = 0; it < 8; ++it) {                 // 2048 chunks / 256 thr
        int i = tid + it * 256;
        int r = i >> 9, rem = i & 511;
        int row = rem >> 3, sub = rem & 7;
        cp_async16(sb + r * 8192 + SWZ(row * 128 + sub * 16),
                   (const char*)g_Azh + (size_t)(bt0 + row) * 512 + r * 128 + sub * 16);
    }
    load_Bslab(sb, 0, tid);
    asm volatile("cp.async.commit_group;" ::: "memory");
    load_Bslab(sb, 1, tid);
    asm volatile("cp.async.commit_group;" ::: "memory");
    load_Bslab(sb, 2, tid);
    asm volatile("cp.async.commit_group;" ::: "memory");

    float Ar[2][2];
    #pragma unroll
    for (int mt = 0; mt < 2; ++mt)
        #pragma unroll
        for (int h = 0; h < 2; ++h)
            Ar[mt][h] = g_A[bt0 + wm * 32 + mt * 16 + h * 8 + (l >> 2)];

    float bd[2][2], bd2[2][2];
    int   bi[2][2];
    #pragma unroll
    for (int mt = 0; mt < 2; ++mt)
        #pragma unroll
        for (int h = 0; h < 2; ++h) {
            bd[mt][h] = __int_as_float(0x7f800000);
            bd2[mt][h] = __int_as_float(0x7f800000);
            bi[mt][h] = 0;
        }

    float acc[2][4][4];
    #pragma unroll
    for (int mt = 0; mt < 2; ++mt)
        #pragma unroll
        for (int nt = 0; nt < 4; ++nt)
            #pragma unroll
            for (int e = 0; e < 4; ++e) acc[mt][nt][e] = 0.0f;

    for (int u = 0; u < nslab; ++u) {
        if (u + 3 < nslab)
            asm volatile("cp.async.wait_group 2;" ::: "memory");
        else
            asm volatile("cp.async.wait_group 0;" ::: "memory");
        __syncthreads();

        if (u + 3 < nslab) {
            load_Bslab(sb, u + 3, tid);
            asm volatile("cp.async.commit_group;" ::: "memory");
        }

        const int ks = u & 3, n = u >> 2;
        const uint32_t abase = sb + ks * 8192;
        const uint32_t bbase = sb + SM_B + (u & 3) * 16384;

        #pragma unroll
        for (int kq = 0; kq < 2; ++kq) {
            uint32_t Bk[4][4];
            #pragma unroll
            for (int nt = 0; nt < 4; ++nt) {
                uint32_t ba = bbase +
                    SWZ((wn * 32 + nt * 8 + (l & 7)) * 128 + kq * 64 + (l >> 3) * 16);
                ldsm4(ba, Bk[nt]);
            }
            uint32_t Aa[2][2][4];
            #pragma unroll
            for (int mt = 0; mt < 2; ++mt)
                #pragma unroll
                for (int kk = 0; kk < 2; ++kk) {
                    uint32_t aa = abase +
                        SWZ((wm * 32 + mt * 16 + (l & 15)) * 128
                            + kq * 64 + kk * 32 + (l >> 4) * 16);
                    ldsm4(aa, Aa[mt][kk]);
                }
            #pragma unroll
            for (int mt = 0; mt < 2; ++mt)
                #pragma unroll
                for (int nt = 0; nt < 4; ++nt) {
                    mma_f16(acc[mt][nt], Aa[mt][0], Bk[nt][0], Bk[nt][1]);
                    mma_f16(acc[mt][nt], Aa[mt][1], Bk[nt][2], Bk[nt][3]);
                }
        }

        if (ks == 3) {
            // chunk epilogue: dist = fl(fl(A - 2d) + C); write to g_D;
            // fold first-min + second-best
            #pragma unroll
            for (int mt = 0; mt < 2; ++mt)
                #pragma unroll
                for (int h = 0; h < 2; ++h) {
                    const int trow = wm * 32 + mt * 16 + h * 8 + (l >> 2);
                    #pragma unroll
                    for (int nt = 0; nt < 4; ++nt) {
                        int c0 = n * 128 + wn * 32 + nt * 8 + (l & 3) * 2;
                        float C0 = __ldg(&g_C[c0]);
                        float C1 = __ldg(&g_C[c0 + 1]);
                        float q0 = __fadd_rn(__fadd_rn(Ar[mt][h],
                                     acc[mt][nt][h * 2 + 0] * -0.001953125f), C0);
                        float q1 = __fadd_rn(__fadd_rn(Ar[mt][h],
                                     acc[mt][nt][h * 2 + 1] * -0.001953125f), C1);
                        float2 qv; qv.x = q0; qv.y = q1;
                        *(float2*)&g_D[(size_t)(bt0 + trow) * NE + c0] = qv;
                        if (q0 < bd[mt][h]) { bd2[mt][h] = bd[mt][h]; bd[mt][h] = q0; bi[mt][h] = c0; }
                        else if (q0 < bd2[mt][h]) bd2[mt][h] = q0;
                        if (q1 < bd[mt][h]) { bd2[mt][h] = bd[mt][h]; bd[mt][h] = q1; bi[mt][h] = c0 + 1; }
                        else if (q1 < bd2[mt][h]) bd2[mt][h] = q1;
                    }
                }
            #pragma unroll
            for (int mt = 0; mt < 2; ++mt)
                #pragma unroll
                for (int nt = 0; nt < 4; ++nt)
                    #pragma unroll
                    for (int e = 0; e < 4; ++e) acc[mt][nt][e] = 0.0f;
        }
    }

    // cross-lane reduce over the 4 lanes sharing each token row
    #pragma unroll
    for (int mt = 0; mt < 2; ++mt)
        #pragma unroll
        for (int h = 0; h < 2; ++h)
            #pragma unroll
            for (int off = 1; off <= 2; off <<= 1) {
                float od  = __shfl_xor_sync(0xffffffffu, bd[mt][h], off);
                int   oi  = __shfl_xor_sync(0xffffffffu, bi[mt][h], off);
                float od2 = __shfl_xor_sync(0xffffffffu, bd2[mt][h], off);
                float mx  = fmaxf(bd[mt][h], od);
                bd2[mt][h] = fminf(fminf(bd2[mt][h], od2), mx);
                if (od < bd[mt][h] || (od == bd[mt][h] && oi < bi[mt][h])) {
                    bd[mt][h] = od; bi[mt][h] = oi;
                }
            }

    __syncthreads();                     // B ring dead; reuse for staging
    float* stD  = (float*)(smem + SM_B);
    int*   stI  = (int*)(smem + SM_B + 1024);
    float* stD2 = (float*)(smem + SM_B + 2048);
    if ((l & 3) == 0) {
        #pragma unroll
        for (int mt = 0; mt < 2; ++mt)
            #pragma unroll
            for (int h = 0; h < 2; ++h) {
                int t = wm * 32 + mt * 16 + h * 8 + (l >> 2);
                stD[t * 4 + wn]  = bd[mt][h];
                stI[t * 4 + wn]  = bi[mt][h];
                stD2[t * 4 + wn] = bd2[mt][h];
            }
    }
    __syncthreads();
    if (tid < 64) {
        float db = stD[tid * 4];
        int   ib = stI[tid * 4];
        float s2 = stD2[tid * 4];
        #pragma unroll
        for (int m = 1; m < 4; ++m) {
            float d = stD[tid * 4 + m];
            int   i = stI[tid * 4 + m];
            float d2 = stD2[tid * 4 + m];
            s2 = fminf(s2, d2);
            if (d < db || (d == db && i < ib)) { s2 = fminf(s2, db); db = d; ib = i; }
            else s2 = fminf(s2, d);
        }
        g_idx[bt0 + tid] = ib;
        g_bd[bt0 + tid]  = db;
        if (s2 - db < TAU) {                      // ambiguous: exact re-check
            int pos = atomicAdd(&g_nflag, 1);
            g_flag[pos] = bt0 + tid;
        }
    }
}

// ---------------------------------------------------------------------------
// Candidate-pruned exact refinement. Warp per flagged token: scan the
// token's 1024 hmma dists, candidates = {c : d < bd + TAU} (superset of
// the true argmin since TAU >= 2*err_max). Each candidate recomputed with
// the exact sequential k-ascending fp32 FMA chain + identical epilogue
// rounding of the proven round-1 kernel; lexicographic (dist, idx) min.
// ---------------------------------------------------------------------------
__global__ void __launch_bounds__(256, 1)
vq_refine_kernel(const float* __restrict__ z, const float* __restrict__ w) {
    __shared__ float zs[8][256];
    const int lane = threadIdx.x & 31, wl = threadIdx.x >> 5;
    const int gw = blockIdx.x * 8 + wl;
    const int nwarp = gridDim.x * 8;
    const int nf = g_nflag;

    for (int it = gw; it < nf; it += nwarp) {
        const int t = g_flag[it];
        float* zr = zs[wl];
        #pragma unroll
        for (int q = 0; q < 2; ++q) {             // coalesced float4 loads
            float4 v = *(const float4*)&z[(size_t)t * D + (lane + q * 32) * 4];
            zr[(lane + q * 32) * 4 + 0] = v.x;
            zr[(lane + q * 32) * 4 + 1] = v.y;
            zr[(lane + q * 32) * 4 + 2] = v.z;
            zr[(lane + q * 32) * 4 + 3] = v.w;
        }
        __syncwarp();
        const float thr = g_bd[t] + TAU;
        const float A   = g_A[t];
        const float* drow = g_D + (size_t)t * NE;

        float bestd = __int_as_float(0x7f800000);
        int   besti = 0x7fffffff;
        for (int c0 = 0; c0 < NE; c0 += 32) {
            float dv = drow[c0 + lane];
            unsigned m = __ballot_sync(0xffffffffu, dv < thr);
            int nc = __popc(m);
            if (nc == 0) continue;
            int myc = -1;
            if (lane < nc) {                       // lane takes its rank-th bit
                unsigned mm = m;
                for (int r = 0; r < lane; ++r) mm &= mm - 1;
                myc = c0 + __ffs(mm) - 1;
            }
            float dist = __int_as_float(0x7f800000);
            if (myc >= 0) {
                float acc = 0.0f;
                const float* wr = w + (size_t)myc * D;
                #pragma unroll 8
                for (int k = 0; k < 256; ++k)      // exact sequential chain
                    acc = fmaf(zr[k], __ldg(&wr[k]), acc);
                dist = __fadd_rn(__fadd_rn(A, -2.0f * acc), __ldg(&g_C[myc]));
            }
            if (myc >= 0 && (dist < bestd || (dist == bestd && myc < besti))) {
                bestd = dist; besti = myc;
            }
        }
        #pragma unroll
        for (int off = 16; off > 0; off >>= 1) {
            float od = __shfl_xor_sync(0xffffffffu, bestd, off);
            int   oi = __shfl_xor_sync(0xffffffffu, besti, off);
            if (od < bestd || (od == bestd && oi < besti)) { bestd = od; besti = oi; }
        }
        if (lane == 0) g_idx[t] = besti;
        __syncwarp();
    }
}

// ---------------------------------------------------------------------------
// Output: warp per token. z_q_st = fl(z + fl(zq-z)); loss = fl(m + fl(.25m))
// ---------------------------------------------------------------------------
__global__ void vq_out_kernel(const float* __restrict__ z, const float* __restrict__ w,
                              float* __restrict__ out_zq, float* __restrict__ out_loss,
                              float* __restrict__ out_idx) {
    int warp = threadIdx.x >> 5, lane = threadIdx.x & 31;
    int t = blockIdx.x * 8 + warp;
    int j = g_idx[t];
    const float4* zp = (const float4*)(z + (size_t)t * D);
    const float4* wp = (const float4*)(w + (size_t)j * D);
    float4* op = (float4*)(out_zq + (size_t)t * D);
    float sq = 0.0f;
    #pragma unroll
    for (int i = 0; i < 2; ++i) {
        float4 zv = zp[lane + 32 * i];
        float4 wv = wp[lane + 32 * i];
        float4 o;
        float d;
        d = __fadd_rn(wv.x, -zv.x); o.x = __fadd_rn(zv.x, d); sq = __fadd_rn(sq, __fmul_rn(d, d));
        d = __fadd_rn(wv.y, -zv.y); o.y = __fadd_rn(zv.y, d); sq = __fadd_rn(sq, __fmul_rn(d, d));
        d = __fadd_rn(wv.z, -zv.z); o.z = __fadd_rn(zv.z, d); sq = __fadd_rn(sq, __fmul_rn(d, d));
        d = __fadd_rn(wv.w, -zv.w); o.w = __fadd_rn(zv.w, d); sq = __fadd_rn(sq, __fmul_rn(d, d));
        op[lane + 32 * i] = o;
    }
    #pragma unroll
    for (int o = 16; o > 0; o >>= 1) sq += __shfl_xor_sync(0xffffffffu, sq, o);
    if (lane == 0) {
        float m = sq * (1.0f / 256.0f);
        out_loss[t] = __fadd_rn(m, __fmul_rn(0.25f, m));
        out_idx[t]  = (float)j;
    }
}

// ---------------------------------------------------------------------------
extern "C" void kernel_launch(void* const* d_in, const int* in_sizes, int n_in,
                              void* d_out, int out_size) {
    const float* z = (const float*)d_in[0];
    const float* w = (const float*)d_in[1];
    const int n  = in_sizes[0] / D;   // 65536
    const int ne = in_sizes[1] / D;   // 1024
    float* out      = (float*)d_out;
    float* out_loss = out + (size_t)n * D;
    float* out_idx  = out_loss + n;

    prep_kernel<<<n / 32, 256>>>(z, 1);
    prep_kernel<<<ne / 32, 256>>>(w, 0);

    cudaFuncSetAttribute(vq_hmma_kernel,
                         cudaFuncAttributeMaxDynamicSharedMemorySize, SM_TOT);
    vq_hmma_kernel<<<n / 64, 256, SM_TOT>>>(ne / 128);

    vq_refine_kernel<<<1024, 256>>>(z, w);

    vq_out_kernel<<<n / 8, 256>>>(z, w, out, out_loss, out_idx);
}

// round 14
// speedup vs baseline: 4.8509x; 1.1359x over previous
#include <cuda_runtime.h>
#include <cuda_fp16.h>
#include <stdint.h>
#include <math.h>

// VectorQuantizer: z [65536,256] f32, W [1024,256] f32.
// dist = ||z||^2 - 2 z.W^T + ||w||^2 ; idx = argmin (first-min tie-break)
// out (f32): z_q_st [N*256] | loss [N] | idx [N]
//
// fp16 HMMA (K=256, w scaled x1024) computes ALL dists, writes them to g_D,
// and tracks per-token best/second-best. Worst-case fp16 dist error
// <= 3.1e-4 per dot => 6.2e-4 on dist; TAU = 7e-4 >= 2*err. Tokens with
// second-best gap < TAU are re-resolved: candidates = {c: d_hmma < bd+TAU}
// (provable superset of true argmin), each recomputed with the exact
// sequential fp32 chain of the proven round-1 kernel; first-min tie-break.

#define D    256
#define NTOK 65536
#define NE   1024
#define TAU  7e-4f

__device__ float g_A[NTOK];
__device__ float g_C[NE];
__device__ float g_bd[NTOK];
__device__ int   g_idx[NTOK];
__device__ int   g_nflag;
__device__ int   g_flag[NTOK];
__device__ __align__(256) float  g_D[(size_t)NTOK * NE];   // hmma dists
__device__ __align__(256) __half g_Azh[(size_t)NTOK * D];
__device__ __align__(256) __half g_Bwh[(size_t)NE * D];

// smem: A resident 4 slabs x 8KB (SW128) + B ring 4 x 16KB
#define SM_B   32768
#define SM_TOT 98304
#define SWZ(o) ((o) ^ (((o) >> 3) & 0x70))

__device__ __forceinline__ uint32_t smem_u32(const void* p) {
    uint32_t a;
    asm("{ .reg .u64 t; cvta.to.shared.u64 t, %1; cvt.u32.u64 %0, t; }" : "=r"(a) : "l"(p));
    return a;
}
__device__ __forceinline__ void cp_async16(uint32_t dst, const void* src) {
    asm volatile("cp.async.cg.shared.global [%0], [%1], 16;" :: "r"(dst), "l"(src) : "memory");
}
__device__ __forceinline__ void ldsm4(uint32_t a, uint32_t r[4]) {
    asm volatile("ldmatrix.sync.aligned.m8n8.x4.shared.b16 {%0,%1,%2,%3}, [%4];"
                 : "=r"(r[0]), "=r"(r[1]), "=r"(r[2]), "=r"(r[3]) : "r"(a));
}
__device__ __forceinline__ void mma_f16(float d[4], const uint32_t a[4],
                                        uint32_t b0, uint32_t b1) {
    asm volatile(
        "mma.sync.aligned.m16n8k16.row.col.f32.f16.f16.f32 "
        "{%0,%1,%2,%3}, {%4,%5,%6,%7}, {%8,%9}, {%0,%1,%2,%3};"
        : "+f"(d[0]), "+f"(d[1]), "+f"(d[2]), "+f"(d[3])
        : "r"(a[0]), "r"(a[1]), "r"(a[2]), "r"(a[3]), "r"(b0), "r"(b1));
}

// ---------------------------------------------------------------------------
// Fused prep: per 32 rows, (a) strictly-sequential fp32 sum-of-squares
// (reference order), (b) fp16 conversion (w scaled x1024). which=1 -> z.
// ---------------------------------------------------------------------------
__global__ void prep_kernel(const float* __restrict__ x, int which) {
    __shared__ float buf[32][257];
    if (which == 0 && blockIdx.x == 0 && threadIdx.x == 0) g_nflag = 0;
    int r0 = blockIdx.x * 32;
    const float scl = which ? 1.0f : 1024.0f;
    __half* dst = which ? g_Azh : g_Bwh;
    for (int i = threadIdx.x; i < 32 * 64; i += 256) {   // 32 rows x 64 float4
        int r = i >> 6, q = (i & 63) * 4;
        float4 v = *(const float4*)&x[(size_t)(r0 + r) * D + q];
        float* b = &buf[r][q];
        b[0] = v.x; b[1] = v.y; b[2] = v.z; b[3] = v.w;
        union { __half h[4]; uint2 u; } p;
        p.h[0] = __float2half(v.x * scl); p.h[1] = __float2half(v.y * scl);
        p.h[2] = __float2half(v.z * scl); p.h[3] = __float2half(v.w * scl);
        *(uint2*)&dst[(size_t)(r0 + r) * D + q] = p.u;
    }
    __syncthreads();
    if (threadIdx.x < 32) {
        int r = threadIdx.x;
        float a = 0.0f;
        #pragma unroll 1
        for (int c = 0; c < 256; ++c) {
            float v = buf[r][c];
            a = __fadd_rn(a, __fmul_rn(v, v));
        }
        if (which) g_A[r0 + r] = a;
        else       g_C[r0 + r] = a;
    }
}

// ---------------------------------------------------------------------------
// B slab loader: slab u -> chunk n = u/4, ks = u%4.
// 128 code rows x 64 fp16 (128B), SW128 into ring buffer (u&3).
// ---------------------------------------------------------------------------
__device__ __forceinline__ void load_Bslab(uint32_t sb, int u, int tid) {
    int n = u >> 2, ks = u & 3;
    size_t src0 = (size_t)(n * 128) * 512 + ks * 128;   // row = 512 bytes
    uint32_t dst0 = sb + SM_B + (u & 3) * 16384;
    #pragma unroll
    for (int it = 0; it < 4; ++it) {                 // 1024 chunks / 256 thr
        int i = tid + it * 256;
        int row = i >> 3, sub = i & 7;
        cp_async16(dst0 + SWZ(row * 128 + sub * 16),
                   (const char*)g_Bwh + src0 + (size_t)row * 512 + sub * 16);
    }
}

// ---------------------------------------------------------------------------
// Fused fp16 HMMA GEMM + argmin (+ dist-matrix write + 2nd-best flagging).
// CTA = 64 tokens, 256 threads (2x4 warps, 32x32 warp tiles). K=256.
// 2 CTAs/SM: 96KB smem + 128 regs/thread each.
// ---------------------------------------------------------------------------
__global__ void __launch_bounds__(256, 2)
vq_hmma_kernel(int nch) {
    extern __shared__ __align__(1024) char smem[];
    uint32_t sb = smem_u32(smem);
    const int tid = threadIdx.x;
    const int l   = tid & 31, w = tid >> 5;
    const int wm  = w >> 2,  wn = w & 3;
    const int bt0 = blockIdx.x * 64;
    const int nslab = nch * 4;

    // group 0: full A (4 slabs x 64 rows x 128B = 32KB) + B slab 0
    #pragma unroll
    for (int it = 0; it < 8; ++it) {                 // 2048 chunks / 256 thr
        int i = tid + it * 256;
        int r = i >> 9, rem = i & 511;
        int row = rem >> 3, sub = rem & 7;
        cp_async16(sb + r * 8192 + SWZ(row * 128 + sub * 16),
                   (const char*)g_Azh + (size_t)(bt0 + row) * 512 + r * 128 + sub * 16);
    }
    load_Bslab(sb, 0, tid);
    asm volatile("cp.async.commit_group;" ::: "memory");
    load_Bslab(sb, 1, tid);
    asm volatile("cp.async.commit_group;" ::: "memory");
    load_Bslab(sb, 2, tid);
    asm volatile("cp.async.commit_group;" ::: "memory");

    float Ar[2][2];
    #pragma unroll
    for (int mt = 0; mt < 2; ++mt)
        #pragma unroll
        for (int h = 0; h < 2; ++h)
            Ar[mt][h] = g_A[bt0 + wm * 32 + mt * 16 + h * 8 + (l >> 2)];

    float bd[2][2], bd2[2][2];
    int   bi[2][2];
    #pragma unroll
    for (int mt = 0; mt < 2; ++mt)
        #pragma unroll
        for (int h = 0; h < 2; ++h) {
            bd[mt][h] = __int_as_float(0x7f800000);
            bd2[mt][h] = __int_as_float(0x7f800000);
            bi[mt][h] = 0;
        }

    float acc[2][4][4];
    #pragma unroll
    for (int mt = 0; mt < 2; ++mt)
        #pragma unroll
        for (int nt = 0; nt < 4; ++nt)
            #pragma unroll
            for (int e = 0; e < 4; ++e) acc[mt][nt][e] = 0.0f;

    for (int u = 0; u < nslab; ++u) {
        if (u + 3 < nslab)
            asm volatile("cp.async.wait_group 2;" ::: "memory");
        else
            asm volatile("cp.async.wait_group 0;" ::: "memory");
        __syncthreads();

        if (u + 3 < nslab) {
            load_Bslab(sb, u + 3, tid);
            asm volatile("cp.async.commit_group;" ::: "memory");
        }

        const int ks = u & 3, n = u >> 2;
        const uint32_t abase = sb + ks * 8192;
        const uint32_t bbase = sb + SM_B + (u & 3) * 16384;

        #pragma unroll
        for (int kq = 0; kq < 2; ++kq) {
            uint32_t Bk[4][4];
            #pragma unroll
            for (int nt = 0; nt < 4; ++nt) {
                uint32_t ba = bbase +
                    SWZ((wn * 32 + nt * 8 + (l & 7)) * 128 + kq * 64 + (l >> 3) * 16);
                ldsm4(ba, Bk[nt]);
            }
            uint32_t Aa[2][2][4];
            #pragma unroll
            for (int mt = 0; mt < 2; ++mt)
                #pragma unroll
                for (int kk = 0; kk < 2; ++kk) {
                    uint32_t aa = abase +
                        SWZ((wm * 32 + mt * 16 + (l & 15)) * 128
                            + kq * 64 + kk * 32 + (l >> 4) * 16);
                    ldsm4(aa, Aa[mt][kk]);
                }
            #pragma unroll
            for (int mt = 0; mt < 2; ++mt)
                #pragma unroll
                for (int nt = 0; nt < 4; ++nt) {
                    mma_f16(acc[mt][nt], Aa[mt][0], Bk[nt][0], Bk[nt][1]);
                    mma_f16(acc[mt][nt], Aa[mt][1], Bk[nt][2], Bk[nt][3]);
                }
        }

        if (ks == 3) {
            // chunk epilogue: dist = fl(fl(A - 2d) + C); write to g_D;
            // fold first-min + second-best
            #pragma unroll
            for (int mt = 0; mt < 2; ++mt)
                #pragma unroll
                for (int h = 0; h < 2; ++h) {
                    const int trow = wm * 32 + mt * 16 + h * 8 + (l >> 2);
                    #pragma unroll
                    for (int nt = 0; nt < 4; ++nt) {
                        int c0 = n * 128 + wn * 32 + nt * 8 + (l & 3) * 2;
                        float C0 = __ldg(&g_C[c0]);
                        float C1 = __ldg(&g_C[c0 + 1]);
                        float q0 = __fadd_rn(__fadd_rn(Ar[mt][h],
                                     acc[mt][nt][h * 2 + 0] * -0.001953125f), C0);
                        float q1 = __fadd_rn(__fadd_rn(Ar[mt][h],
                                     acc[mt][nt][h * 2 + 1] * -0.001953125f), C1);
                        float2 qv; qv.x = q0; qv.y = q1;
                        *(float2*)&g_D[(size_t)(bt0 + trow) * NE + c0] = qv;
                        if (q0 < bd[mt][h]) { bd2[mt][h] = bd[mt][h]; bd[mt][h] = q0; bi[mt][h] = c0; }
                        else if (q0 < bd2[mt][h]) bd2[mt][h] = q0;
                        if (q1 < bd[mt][h]) { bd2[mt][h] = bd[mt][h]; bd[mt][h] = q1; bi[mt][h] = c0 + 1; }
                        else if (q1 < bd2[mt][h]) bd2[mt][h] = q1;
                    }
                }
            #pragma unroll
            for (int mt = 0; mt < 2; ++mt)
                #pragma unroll
                for (int nt = 0; nt < 4; ++nt)
                    #pragma unroll
                    for (int e = 0; e < 4; ++e) acc[mt][nt][e] = 0.0f;
        }
    }

    // cross-lane reduce over the 4 lanes sharing each token row
    #pragma unroll
    for (int mt = 0; mt < 2; ++mt)
        #pragma unroll
        for (int h = 0; h < 2; ++h)
            #pragma unroll
            for (int off = 1; off <= 2; off <<= 1) {
                float od  = __shfl_xor_sync(0xffffffffu, bd[mt][h], off);
                int   oi  = __shfl_xor_sync(0xffffffffu, bi[mt][h], off);
                float od2 = __shfl_xor_sync(0xffffffffu, bd2[mt][h], off);
                float mx  = fmaxf(bd[mt][h], od);
                bd2[mt][h] = fminf(fminf(bd2[mt][h], od2), mx);
                if (od < bd[mt][h] || (od == bd[mt][h] && oi < bi[mt][h])) {
                    bd[mt][h] = od; bi[mt][h] = oi;
                }
            }

    __syncthreads();                     // B ring dead; reuse for staging
    float* stD  = (float*)(smem + SM_B);
    int*   stI  = (int*)(smem + SM_B + 1024);
    float* stD2 = (float*)(smem + SM_B + 2048);
    if ((l & 3) == 0) {
        #pragma unroll
        for (int mt = 0; mt < 2; ++mt)
            #pragma unroll
            for (int h = 0; h < 2; ++h) {
                int t = wm * 32 + mt * 16 + h * 8 + (l >> 2);
                stD[t * 4 + wn]  = bd[mt][h];
                stI[t * 4 + wn]  = bi[mt][h];
                stD2[t * 4 + wn] = bd2[mt][h];
            }
    }
    __syncthreads();
    if (tid < 64) {
        float db = stD[tid * 4];
        int   ib = stI[tid * 4];
        float s2 = stD2[tid * 4];
        #pragma unroll
        for (int m = 1; m < 4; ++m) {
            float d = stD[tid * 4 + m];
            int   i = stI[tid * 4 + m];
            float d2 = stD2[tid * 4 + m];
            s2 = fminf(s2, d2);
            if (d < db || (d == db && i < ib)) { s2 = fminf(s2, db); db = d; ib = i; }
            else s2 = fminf(s2, d);
        }
        g_idx[bt0 + tid] = ib;
        g_bd[bt0 + tid]  = db;
        if (s2 - db < TAU) {                      // ambiguous: exact re-check
            int pos = atomicAdd(&g_nflag, 1);
            g_flag[pos] = bt0 + tid;
        }
    }
}

// ---------------------------------------------------------------------------
// Candidate-pruned exact refinement, MLP-32 scan + single-phase chains.
// Warp per flagged token: prefetch all 1024 hmma dists into registers
// (32 independent coalesced loads), ballot on register values, assign
// global candidate ranks so all candidates (usually <32) run their exact
// chains concurrently in ONE phase. Chain arithmetic identical to the
// proven round-1 kernel; lexicographic (dist, idx) min.
// ---------------------------------------------------------------------------
__global__ void __launch_bounds__(256, 1)
vq_refine_kernel(const float* __restrict__ z, const float* __restrict__ w) {
    __shared__ float zs[8][256];
    const int lane = threadIdx.x & 31, wl = threadIdx.x >> 5;
    const int gw = blockIdx.x * 8 + wl;
    const int nwarp = gridDim.x * 8;
    const int nf = g_nflag;

    for (int it = gw; it < nf; it += nwarp) {
        const int t = g_flag[it];
        const float* drow = g_D + (size_t)t * NE;

        // MLP-32 prefetch of the full dist row (coalesced: lane*4B apart)
        float dv[32];
        #pragma unroll
        for (int i = 0; i < 32; ++i) dv[i] = drow[i * 32 + lane];

        float* zr = zs[wl];
        #pragma unroll
        for (int q = 0; q < 2; ++q) {             // coalesced float4 loads
            float4 v = *(const float4*)&z[(size_t)t * D + (lane + q * 32) * 4];
            zr[(lane + q * 32) * 4 + 0] = v.x;
            zr[(lane + q * 32) * 4 + 1] = v.y;
            zr[(lane + q * 32) * 4 + 2] = v.z;
            zr[(lane + q * 32) * 4 + 3] = v.w;
        }
        __syncwarp();
        const float thr = g_bd[t] + TAU;
        const float A   = g_A[t];

        float bestd = __int_as_float(0x7f800000);
        int   besti = 0x7fffffff;

        int done = 0;
        while (true) {
            // assign candidates with global ranks [done, done+32) to lanes
            int myc = -1, seen = 0;
            #pragma unroll
            for (int i = 0; i < 32; ++i) {
                unsigned m = __ballot_sync(0xffffffffu, dv[i] < thr);
                int nc = __popc(m);
                int r = lane + done - seen;        // my rank within chunk i
                if (r >= 0 && r < nc) {
                    unsigned mm = m;
                    for (int k = 0; k < r; ++k) mm &= mm - 1;
                    myc = i * 32 + __ffs(mm) - 1;
                }
                seen += nc;
            }
            if (myc >= 0) {                        // one exact chain per lane
                float acc = 0.0f;
                const float* wr = w + (size_t)myc * D;
                #pragma unroll 8
                for (int k = 0; k < 256; ++k)      // exact sequential chain
                    acc = fmaf(zr[k], __ldg(&wr[k]), acc);
                float dist = __fadd_rn(__fadd_rn(A, -2.0f * acc), __ldg(&g_C[myc]));
                if (dist < bestd || (dist == bestd && myc < besti)) {
                    bestd = dist; besti = myc;
                }
            }
            done += 32;
            if (done >= seen) break;               // usually one phase
        }

        #pragma unroll
        for (int off = 16; off > 0; off >>= 1) {
            float od = __shfl_xor_sync(0xffffffffu, bestd, off);
            int   oi = __shfl_xor_sync(0xffffffffu, besti, off);
            if (od < bestd || (od == bestd && oi < besti)) { bestd = od; besti = oi; }
        }
        if (lane == 0) g_idx[t] = besti;
        __syncwarp();
    }
}

// ---------------------------------------------------------------------------
// Output: warp per token. z_q_st = fl(z + fl(zq-z)); loss = fl(m + fl(.25m))
// ---------------------------------------------------------------------------
__global__ void vq_out_kernel(const float* __restrict__ z, const float* __restrict__ w,
                              float* __restrict__ out_zq, float* __restrict__ out_loss,
                              float* __restrict__ out_idx) {
    int warp = threadIdx.x >> 5, lane = threadIdx.x & 31;
    int t = blockIdx.x * 8 + warp;
    int j = g_idx[t];
    const float4* zp = (const float4*)(z + (size_t)t * D);
    const float4* wp = (const float4*)(w + (size_t)j * D);
    float4* op = (float4*)(out_zq + (size_t)t * D);
    float sq = 0.0f;
    #pragma unroll
    for (int i = 0; i < 2; ++i) {
        float4 zv = zp[lane + 32 * i];
        float4 wv = wp[lane + 32 * i];
        float4 o;
        float d;
        d = __fadd_rn(wv.x, -zv.x); o.x = __fadd_rn(zv.x, d); sq = __fadd_rn(sq, __fmul_rn(d, d));
        d = __fadd_rn(wv.y, -zv.y); o.y = __fadd_rn(zv.y, d); sq = __fadd_rn(sq, __fmul_rn(d, d));
        d = __fadd_rn(wv.z, -zv.z); o.z = __fadd_rn(zv.z, d); sq = __fadd_rn(sq, __fmul_rn(d, d));
        d = __fadd_rn(wv.w, -zv.w); o.w = __fadd_rn(zv.w, d); sq = __fadd_rn(sq, __fmul_rn(d, d));
        op[lane + 32 * i] = o;
    }
    #pragma unroll
    for (int o = 16; o > 0; o >>= 1) sq += __shfl_xor_sync(0xffffffffu, sq, o);
    if (lane == 0) {
        float m = sq * (1.0f / 256.0f);
        out_loss[t] = __fadd_rn(m, __fmul_rn(0.25f, m));
        out_idx[t]  = (float)j;
    }
}

// ---------------------------------------------------------------------------
extern "C" void kernel_launch(void* const* d_in, const int* in_sizes, int n_in,
                              void* d_out, int out_size) {
    const float* z = (const float*)d_in[0];
    const float* w = (const float*)d_in[1];
    const int n  = in_sizes[0] / D;   // 65536
    const int ne = in_sizes[1] / D;   // 1024
    float* out      = (float*)d_out;
    float* out_loss = out + (size_t)n * D;
    float* out_idx  = out_loss + n;

    prep_kernel<<<n / 32, 256>>>(z, 1);
    prep_kernel<<<ne / 32, 256>>>(w, 0);

    cudaFuncSetAttribute(vq_hmma_kernel,
                         cudaFuncAttributeMaxDynamicSharedMemorySize, SM_TOT);
    vq_hmma_kernel<<<n / 64, 256, SM_TOT>>>(ne / 128);

    vq_refine_kernel<<<1024, 256>>>(z, w);

    vq_out_kernel<<<n / 8, 256>>>(z, w, out, out_loss, out_idx);
}

// round 15
// speedup vs baseline: 5.1110x; 1.0536x over previous
#include <cuda_runtime.h>
#include <cuda_fp16.h>
#include <stdint.h>
#include <math.h>

// VectorQuantizer: z [65536,256] f32, W [1024,256] f32.
// dist = ||z||^2 - 2 z.W^T + ||w||^2 ; idx = argmin (first-min tie-break)
// out (f32): z_q_st [N*256] | loss [N] | idx [N]
//
// fp16 HMMA (K=256, w scaled x1024) computes ALL dists, tracks per-token
// best/second-best (fp32), and stores dist-A as fp16 (Sterbenz: q-A exact
// in fp32; fp16 quantization <= 3e-5). Worst-case fp16 dist error 6.2e-4;
// flag TAU = 7e-4 (fp32 q's). Refine scan threshold TAU_SCAN = 8e-4 >=
// 2*(err+qerr) keeps the candidate set a provable superset of the true
// argmin; candidates recomputed with the exact sequential fp32 chain of
// the proven round-1 kernel; first-min tie-break.

#define D    256
#define NTOK 65536
#define NE   1024
#define TAU      7e-4f
#define TAU_SCAN 8e-4f

__device__ float g_A[NTOK];
__device__ float g_C[NE];
__device__ float g_bd[NTOK];
__device__ int   g_idx[NTOK];
__device__ int   g_nflag;
__device__ int   g_flag[NTOK];
__device__ __align__(256) __half g_Dh[(size_t)NTOK * NE];  // dist - A (fp16)
__device__ __align__(256) __half g_Azh[(size_t)NTOK * D];
__device__ __align__(256) __half g_Bwh[(size_t)NE * D];

// smem: A resident 4 slabs x 8KB (SW128) + B ring 4 x 16KB
#define SM_B   32768
#define SM_TOT 98304
#define SWZ(o) ((o) ^ (((o) >> 3) & 0x70))

__device__ __forceinline__ uint32_t smem_u32(const void* p) {
    uint32_t a;
    asm("{ .reg .u64 t; cvta.to.shared.u64 t, %1; cvt.u32.u64 %0, t; }" : "=r"(a) : "l"(p));
    return a;
}
__device__ __forceinline__ void cp_async16(uint32_t dst, const void* src) {
    asm volatile("cp.async.cg.shared.global [%0], [%1], 16;" :: "r"(dst), "l"(src) : "memory");
}
__device__ __forceinline__ void ldsm4(uint32_t a, uint32_t r[4]) {
    asm volatile("ldmatrix.sync.aligned.m8n8.x4.shared.b16 {%0,%1,%2,%3}, [%4];"
                 : "=r"(r[0]), "=r"(r[1]), "=r"(r[2]), "=r"(r[3]) : "r"(a));
}
__device__ __forceinline__ void mma_f16(float d[4], const uint32_t a[4],
                                        uint32_t b0, uint32_t b1) {
    asm volatile(
        "mma.sync.aligned.m16n8k16.row.col.f32.f16.f16.f32 "
        "{%0,%1,%2,%3}, {%4,%5,%6,%7}, {%8,%9}, {%0,%1,%2,%3};"
        : "+f"(d[0]), "+f"(d[1]), "+f"(d[2]), "+f"(d[3])
        : "r"(a[0]), "r"(a[1]), "r"(a[2]), "r"(a[3]), "r"(b0), "r"(b1));
}

// ---------------------------------------------------------------------------
// Fused prep (single launch): blocks [0, n/32) do z, rest do w.
// Per 32 rows: strictly-sequential fp32 sum-of-squares (reference order)
// + fp16 conversion (w scaled x1024).
// ---------------------------------------------------------------------------
__global__ void prep_kernel(const float* __restrict__ z,
                            const float* __restrict__ w, int nzblk) {
    __shared__ float buf[32][257];
    if (blockIdx.x == 0 && threadIdx.x == 0) g_nflag = 0;
    const int which = (blockIdx.x < nzblk) ? 1 : 0;
    const float* x = which ? z : w;
    int r0 = (which ? blockIdx.x : blockIdx.x - nzblk) * 32;
    const float scl = which ? 1.0f : 1024.0f;
    __half* dst = which ? g_Azh : g_Bwh;
    for (int i = threadIdx.x; i < 32 * 64; i += 256) {   // 32 rows x 64 float4
        int r = i >> 6, q = (i & 63) * 4;
        float4 v = *(const float4*)&x[(size_t)(r0 + r) * D + q];
        float* b = &buf[r][q];
        b[0] = v.x; b[1] = v.y; b[2] = v.z; b[3] = v.w;
        union { __half h[4]; uint2 u; } p;
        p.h[0] = __float2half(v.x * scl); p.h[1] = __float2half(v.y * scl);
        p.h[2] = __float2half(v.z * scl); p.h[3] = __float2half(v.w * scl);
        *(uint2*)&dst[(size_t)(r0 + r) * D + q] = p.u;
    }
    __syncthreads();
    if (threadIdx.x < 32) {
        int r = threadIdx.x;
        float a = 0.0f;
        #pragma unroll 1
        for (int c = 0; c < 256; ++c) {
            float v = buf[r][c];
            a = __fadd_rn(a, __fmul_rn(v, v));
        }
        if (which) g_A[r0 + r] = a;
        else       g_C[r0 + r] = a;
    }
}

// ---------------------------------------------------------------------------
// B slab loader: slab u -> chunk n = u/4, ks = u%4.
// 128 code rows x 64 fp16 (128B), SW128 into ring buffer (u&3).
// ---------------------------------------------------------------------------
__device__ __forceinline__ void load_Bslab(uint32_t sb, int u, int tid) {
    int n = u >> 2, ks = u & 3;
    size_t src0 = (size_t)(n * 128) * 512 + ks * 128;   // row = 512 bytes
    uint32_t dst0 = sb + SM_B + (u & 3) * 16384;
    #pragma unroll
    for (int it = 0; it < 4; ++it) {                 // 1024 chunks / 256 thr
        int i = tid + it * 256;
        int row = i >> 3, sub = i & 7;
        cp_async16(dst0 + SWZ(row * 128 + sub * 16),
                   (const char*)g_Bwh + src0 + (size_t)row * 512 + sub * 16);
    }
}

// ---------------------------------------------------------------------------
// Fused fp16 HMMA GEMM + argmin (+ fp16 dist-A store + 2nd-best flagging).
// CTA = 64 tokens, 256 threads (2x4 warps, 32x32 warp tiles). K=256.
// 2 CTAs/SM: 96KB smem + 128 regs/thread each.
// ---------------------------------------------------------------------------
__global__ void __launch_bounds__(256, 2)
vq_hmma_kernel(int nch) {
    extern __shared__ __align__(1024) char smem[];
    uint32_t sb = smem_u32(smem);
    const int tid = threadIdx.x;
    const int l   = tid & 31, w = tid >> 5;
    const int wm  = w >> 2,  wn = w & 3;
    const int bt0 = blockIdx.x * 64;
    const int nslab = nch * 4;

    // group 0: full A (4 slabs x 64 rows x 128B = 32KB) + B slab 0
    #pragma unroll
    for (int it = 0; it < 8; ++it) {                 // 2048 chunks / 256 thr
        int i = tid + it * 256;
        int r = i >> 9, rem = i & 511;
        int row = rem >> 3, sub = rem & 7;
        cp_async16(sb + r * 8192 + SWZ(row * 128 + sub * 16),
                   (const char*)g_Azh + (size_t)(bt0 + row) * 512 + r * 128 + sub * 16);
    }
    load_Bslab(sb, 0, tid);
    asm volatile("cp.async.commit_group;" ::: "memory");
    load_Bslab(sb, 1, tid);
    asm volatile("cp.async.commit_group;" ::: "memory");
    load_Bslab(sb, 2, tid);
    asm volatile("cp.async.commit_group;" ::: "memory");

    float Ar[2][2];
    #pragma unroll
    for (int mt = 0; mt < 2; ++mt)
        #pragma unroll
        for (int h = 0; h < 2; ++h)
            Ar[mt][h] = g_A[bt0 + wm * 32 + mt * 16 + h * 8 + (l >> 2)];

    float bd[2][2], bd2[2][2];
    int   bi[2][2];
    #pragma unroll
    for (int mt = 0; mt < 2; ++mt)
        #pragma unroll
        for (int h = 0; h < 2; ++h) {
            bd[mt][h] = __int_as_float(0x7f800000);
            bd2[mt][h] = __int_as_float(0x7f800000);
            bi[mt][h] = 0;
        }

    float acc[2][4][4];
    #pragma unroll
    for (int mt = 0; mt < 2; ++mt)
        #pragma unroll
        for (int nt = 0; nt < 4; ++nt)
            #pragma unroll
            for (int e = 0; e < 4; ++e) acc[mt][nt][e] = 0.0f;

    for (int u = 0; u < nslab; ++u) {
        if (u + 3 < nslab)
            asm volatile("cp.async.wait_group 2;" ::: "memory");
        else
            asm volatile("cp.async.wait_group 0;" ::: "memory");
        __syncthreads();

        if (u + 3 < nslab) {
            load_Bslab(sb, u + 3, tid);
            asm volatile("cp.async.commit_group;" ::: "memory");
        }

        const int ks = u & 3, n = u >> 2;
        const uint32_t abase = sb + ks * 8192;
        const uint32_t bbase = sb + SM_B + (u & 3) * 16384;

        #pragma unroll
        for (int kq = 0; kq < 2; ++kq) {
            uint32_t Bk[4][4];
            #pragma unroll
            for (int nt = 0; nt < 4; ++nt) {
                uint32_t ba = bbase +
                    SWZ((wn * 32 + nt * 8 + (l & 7)) * 128 + kq * 64 + (l >> 3) * 16);
                ldsm4(ba, Bk[nt]);
            }
            uint32_t Aa[2][2][4];
            #pragma unroll
            for (int mt = 0; mt < 2; ++mt)
                #pragma unroll
                for (int kk = 0; kk < 2; ++kk) {
                    uint32_t aa = abase +
                        SWZ((wm * 32 + mt * 16 + (l & 15)) * 128
                            + kq * 64 + kk * 32 + (l >> 4) * 16);
                    ldsm4(aa, Aa[mt][kk]);
                }
            #pragma unroll
            for (int mt = 0; mt < 2; ++mt)
                #pragma unroll
                for (int nt = 0; nt < 4; ++nt) {
                    mma_f16(acc[mt][nt], Aa[mt][0], Bk[nt][0], Bk[nt][1]);
                    mma_f16(acc[mt][nt], Aa[mt][1], Bk[nt][2], Bk[nt][3]);
                }
        }

        if (ks == 3) {
            // chunk epilogue: q = fl(fl(A - 2d) + C); store fp16(q - A)
            // (Sterbenz-exact subtraction); fold first-min + second-best
            #pragma unroll
            for (int mt = 0; mt < 2; ++mt)
                #pragma unroll
                for (int h = 0; h < 2; ++h) {
                    const int trow = wm * 32 + mt * 16 + h * 8 + (l >> 2);
                    #pragma unroll
                    for (int nt = 0; nt < 4; ++nt) {
                        int c0 = n * 128 + wn * 32 + nt * 8 + (l & 3) * 2;
                        float C0 = __ldg(&g_C[c0]);
                        float C1 = __ldg(&g_C[c0 + 1]);
                        float q0 = __fadd_rn(__fadd_rn(Ar[mt][h],
                                     acc[mt][nt][h * 2 + 0] * -0.001953125f), C0);
                        float q1 = __fadd_rn(__fadd_rn(Ar[mt][h],
                                     acc[mt][nt][h * 2 + 1] * -0.001953125f), C1);
                        __half2 hv;
                        hv.x = __float2half(__fadd_rn(q0, -Ar[mt][h]));
                        hv.y = __float2half(__fadd_rn(q1, -Ar[mt][h]));
                        *(__half2*)&g_Dh[(size_t)(bt0 + trow) * NE + c0] = hv;
                        if (q0 < bd[mt][h]) { bd2[mt][h] = bd[mt][h]; bd[mt][h] = q0; bi[mt][h] = c0; }
                        else if (q0 < bd2[mt][h]) bd2[mt][h] = q0;
                        if (q1 < bd[mt][h]) { bd2[mt][h] = bd[mt][h]; bd[mt][h] = q1; bi[mt][h] = c0 + 1; }
                        else if (q1 < bd2[mt][h]) bd2[mt][h] = q1;
                    }
                }
            #pragma unroll
            for (int mt = 0; mt < 2; ++mt)
                #pragma unroll
                for (int nt = 0; nt < 4; ++nt)
                    #pragma unroll
                    for (int e = 0; e < 4; ++e) acc[mt][nt][e] = 0.0f;
        }
    }

    // cross-lane reduce over the 4 lanes sharing each token row
    #pragma unroll
    for (int mt = 0; mt < 2; ++mt)
        #pragma unroll
        for (int h = 0; h < 2; ++h)
            #pragma unroll
            for (int off = 1; off <= 2; off <<= 1) {
                float od  = __shfl_xor_sync(0xffffffffu, bd[mt][h], off);
                int   oi  = __shfl_xor_sync(0xffffffffu, bi[mt][h], off);
                float od2 = __shfl_xor_sync(0xffffffffu, bd2[mt][h], off);
                float mx  = fmaxf(bd[mt][h], od);
                bd2[mt][h] = fminf(fminf(bd2[mt][h], od2), mx);
                if (od < bd[mt][h] || (od == bd[mt][h] && oi < bi[mt][h])) {
                    bd[mt][h] = od; bi[mt][h] = oi;
                }
            }

    __syncthreads();                     // B ring dead; reuse for staging
    float* stD  = (float*)(smem + SM_B);
    int*   stI  = (int*)(smem + SM_B + 1024);
    float* stD2 = (float*)(smem + SM_B + 2048);
    if ((l & 3) == 0) {
        #pragma unroll
        for (int mt = 0; mt < 2; ++mt)
            #pragma unroll
            for (int h = 0; h < 2; ++h) {
                int t = wm * 32 + mt * 16 + h * 8 + (l >> 2);
                stD[t * 4 + wn]  = bd[mt][h];
                stI[t * 4 + wn]  = bi[mt][h];
                stD2[t * 4 + wn] = bd2[mt][h];
            }
    }
    __syncthreads();
    if (tid < 64) {
        float db = stD[tid * 4];
        int   ib = stI[tid * 4];
        float s2 = stD2[tid * 4];
        #pragma unroll
        for (int m = 1; m < 4; ++m) {
            float d = stD[tid * 4 + m];
            int   i = stI[tid * 4 + m];
            float d2 = stD2[tid * 4 + m];
            s2 = fminf(s2, d2);
            if (d < db || (d == db && i < ib)) { s2 = fminf(s2, db); db = d; ib = i; }
            else s2 = fminf(s2, d);
        }
        g_idx[bt0 + tid] = ib;
        g_bd[bt0 + tid]  = db;
        if (s2 - db < TAU) {                      // ambiguous: exact re-check
            int pos = atomicAdd(&g_nflag, 1);
            g_flag[pos] = bt0 + tid;
        }
    }
}

// ---------------------------------------------------------------------------
// Candidate-pruned exact refinement, MLP-32 scan + single-phase chains.
// Warp per flagged token: prefetch the full fp16 (dist-A) row (32 coalesced
// loads), threshold against (bd-A)+TAU_SCAN, assign global candidate ranks
// so all candidates run their exact chains concurrently in ONE phase.
// Chain arithmetic identical to the proven round-1 kernel; lexicographic
// (dist, idx) min.
// ---------------------------------------------------------------------------
__global__ void __launch_bounds__(256, 1)
vq_refine_kernel(const float* __restrict__ z, const float* __restrict__ w) {
    __shared__ float zs[8][256];
    const int lane = threadIdx.x & 31, wl = threadIdx.x >> 5;
    const int gw = blockIdx.x * 8 + wl;
    const int nwarp = gridDim.x * 8;
    const int nf = g_nflag;

    for (int it = gw; it < nf; it += nwarp) {
        const int t = g_flag[it];
        const __half* drow = g_Dh + (size_t)t * NE;

        // MLP-32 prefetch of the full relative-dist row
        float dv[32];
        #pragma unroll
        for (int i = 0; i < 32; ++i) dv[i] = __half2float(drow[i * 32 + lane]);

        float* zr = zs[wl];
        #pragma unroll
        for (int q = 0; q < 2; ++q) {             // coalesced float4 loads
            float4 v = *(const float4*)&z[(size_t)t * D + (lane + q * 32) * 4];
            zr[(lane + q * 32) * 4 + 0] = v.x;
            zr[(lane + q * 32) * 4 + 1] = v.y;
            zr[(lane + q * 32) * 4 + 2] = v.z;
            zr[(lane + q * 32) * 4 + 3] = v.w;
        }
        __syncwarp();
        const float A   = g_A[t];
        const float thr = __fadd_rn(g_bd[t], -A) + TAU_SCAN;  // relative thr

        float bestd = __int_as_float(0x7f800000);
        int   besti = 0x7fffffff;

        int done = 0;
        while (true) {
            // assign candidates with global ranks [done, done+32) to lanes
            int myc = -1, seen = 0;
            #pragma unroll
            for (int i = 0; i < 32; ++i) {
                unsigned m = __ballot_sync(0xffffffffu, dv[i] < thr);
                int nc = __popc(m);
                int r = lane + done - seen;        // my rank within chunk i
                if (r >= 0 && r < nc) {
                    unsigned mm = m;
                    for (int k = 0; k < r; ++k) mm &= mm - 1;
                    myc = i * 32 + __ffs(mm) - 1;
                }
                seen += nc;
            }
            if (myc >= 0) {                        // one exact chain per lane
                float acc = 0.0f;
                const float* wr = w + (size_t)myc * D;
                #pragma unroll 8
                for (int k = 0; k < 256; ++k)      // exact sequential chain
                    acc = fmaf(zr[k], __ldg(&wr[k]), acc);
                float dist = __fadd_rn(__fadd_rn(A, -2.0f * acc), __ldg(&g_C[myc]));
                if (dist < bestd || (dist == bestd && myc < besti)) {
                    bestd = dist; besti = myc;
                }
            }
            done += 32;
            if (done >= seen) break;               // usually one phase
        }

        #pragma unroll
        for (int off = 16; off > 0; off >>= 1) {
            float od = __shfl_xor_sync(0xffffffffu, bestd, off);
            int   oi = __shfl_xor_sync(0xffffffffu, besti, off);
            if (od < bestd || (od == bestd && oi < besti)) { bestd = od; besti = oi; }
        }
        if (lane == 0) g_idx[t] = besti;
        __syncwarp();
    }
}

// ---------------------------------------------------------------------------
// Output: warp per 4 tokens (prefetched indices + grouped loads for MLP).
// z_q_st = fl(z + fl(zq-z)); loss = fl(m + fl(.25m))
// ---------------------------------------------------------------------------
__global__ void vq_out_kernel(const float* __restrict__ z, const float* __restrict__ w,
                              float* __restrict__ out_zq, float* __restrict__ out_loss,
                              float* __restrict__ out_idx) {
    int warp = threadIdx.x >> 5, lane = threadIdx.x & 31;
    int t0 = (blockIdx.x * 8 + warp) * 4;

    int j[4];
    #pragma unroll
    for (int i = 0; i < 4; ++i) j[i] = __ldg(&g_idx[t0 + i]);

    float4 zv[4][2], wv[4][2];
    #pragma unroll
    for (int i = 0; i < 4; ++i) {
        const float4* zp = (const float4*)(z + (size_t)(t0 + i) * D);
        const float4* wp = (const float4*)(w + (size_t)j[i] * D);
        #pragma unroll
        for (int q = 0; q < 2; ++q) {
            zv[i][q] = zp[lane + 32 * q];
            wv[i][q] = wp[lane + 32 * q];
        }
    }

    #pragma unroll
    for (int i = 0; i < 4; ++i) {
        float4* op = (float4*)(out_zq + (size_t)(t0 + i) * D);
        float sq = 0.0f;
        #pragma unroll
        for (int q = 0; q < 2; ++q) {
            float4 o;
            float d;
            d = __fadd_rn(wv[i][q].x, -zv[i][q].x); o.x = __fadd_rn(zv[i][q].x, d); sq = __fadd_rn(sq, __fmul_rn(d, d));
            d = __fadd_rn(wv[i][q].y, -zv[i][q].y); o.y = __fadd_rn(zv[i][q].y, d); sq = __fadd_rn(sq, __fmul_rn(d, d));
            d = __fadd_rn(wv[i][q].z, -zv[i][q].z); o.z = __fadd_rn(zv[i][q].z, d); sq = __fadd_rn(sq, __fmul_rn(d, d));
            d = __fadd_rn(wv[i][q].w, -zv[i][q].w); o.w = __fadd_rn(zv[i][q].w, d); sq = __fadd_rn(sq, __fmul_rn(d, d));
            op[lane + 32 * q] = o;
        }
        #pragma unroll
        for (int o = 16; o > 0; o >>= 1) sq += __shfl_xor_sync(0xffffffffu, sq, o);
        if (lane == 0) {
            float m = sq * (1.0f / 256.0f);
            out_loss[t0 + i] = __fadd_rn(m, __fmul_rn(0.25f, m));
            out_idx[t0 + i]  = (float)j[i];
        }
    }
}

// ---------------------------------------------------------------------------
extern "C" void kernel_launch(void* const* d_in, const int* in_sizes, int n_in,
                              void* d_out, int out_size) {
    const float* z = (const float*)d_in[0];
    const float* w = (const float*)d_in[1];
    const int n  = in_sizes[0] / D;   // 65536
    const int ne = in_sizes[1] / D;   // 1024
    float* out      = (float*)d_out;
    float* out_loss = out + (size_t)n * D;
    float* out_idx  = out_loss + n;

    prep_kernel<<<n / 32 + ne / 32, 256>>>(z, w, n / 32);

    cudaFuncSetAttribute(vq_hmma_kernel,
                         cudaFuncAttributeMaxDynamicSharedMemorySize, SM_TOT);
    vq_hmma_kernel<<<n / 64, 256, SM_TOT>>>(ne / 128);

    vq_refine_kernel<<<1024, 256>>>(z, w);

    vq_out_kernel<<<n / 32, 256>>>(z, w, out, out_loss, out_idx);
}

// round 16
// speedup vs baseline: 5.1379x; 1.0053x over previous
#include <cuda_runtime.h>
#include <cuda_fp16.h>
#include <stdint.h>
#include <math.h>

// VectorQuantizer: z [65536,256] f32, W [1024,256] f32.
// dist = ||z||^2 - 2 z.W^T + ||w||^2 ; idx = argmin (first-min tie-break)
// out (f32): z_q_st [N*256] | loss [N] | idx [N]
//
// fp16 HMMA (K=256, w scaled x1024) computes ALL dists, tracks per-token
// best/second-best (fp32), and stores dist-A as fp16 (Sterbenz: q-A exact
// in fp32; fp16 quantization <= 3e-5). Worst-case fp16 dist error 6.2e-4;
// flag TAU = 7e-4 (fp32 q's). Refine scan threshold TAU_SCAN = 8e-4 >=
// 2*(err+qerr) keeps the candidate set a provable superset of the true
// argmin; candidates recomputed with the exact sequential fp32 chain of
// the proven round-1 kernel; first-min tie-break.

#define D    256
#define NTOK 65536
#define NE   1024
#define TAU      7e-4f
#define TAU_SCAN 8e-4f

__device__ float g_A[NTOK];
__device__ float g_C[NE];
__device__ float g_bd[NTOK];
__device__ int   g_idx[NTOK];
__device__ int   g_nflag;
__device__ int   g_flag[NTOK];
__device__ __align__(256) __half g_Dh[(size_t)NTOK * NE];  // dist - A (fp16)
__device__ __align__(256) __half g_Azh[(size_t)NTOK * D];
__device__ __align__(256) __half g_Bwh[(size_t)NE * D];

// smem: A resident 4 slabs x 8KB (SW128) + B ring 4 x 16KB
#define SM_B   32768
#define SM_TOT 98304
#define SWZ(o) ((o) ^ (((o) >> 3) & 0x70))

__device__ __forceinline__ uint32_t smem_u32(const void* p) {
    uint32_t a;
    asm("{ .reg .u64 t; cvta.to.shared.u64 t, %1; cvt.u32.u64 %0, t; }" : "=r"(a) : "l"(p));
    return a;
}
__device__ __forceinline__ void cp_async16(uint32_t dst, const void* src) {
    asm volatile("cp.async.cg.shared.global [%0], [%1], 16;" :: "r"(dst), "l"(src) : "memory");
}
__device__ __forceinline__ void ldsm4(uint32_t a, uint32_t r[4]) {
    asm volatile("ldmatrix.sync.aligned.m8n8.x4.shared.b16 {%0,%1,%2,%3}, [%4];"
                 : "=r"(r[0]), "=r"(r[1]), "=r"(r[2]), "=r"(r[3]) : "r"(a));
}
__device__ __forceinline__ void mma_f16(float d[4], const uint32_t a[4],
                                        uint32_t b0, uint32_t b1) {
    asm volatile(
        "mma.sync.aligned.m16n8k16.row.col.f32.f16.f16.f32 "
        "{%0,%1,%2,%3}, {%4,%5,%6,%7}, {%8,%9}, {%0,%1,%2,%3};"
        : "+f"(d[0]), "+f"(d[1]), "+f"(d[2]), "+f"(d[3])
        : "r"(a[0]), "r"(a[1]), "r"(a[2]), "r"(a[3]), "r"(b0), "r"(b1));
}

// ---------------------------------------------------------------------------
__global__ void reset_kernel() { g_nflag = 0; }

// ---------------------------------------------------------------------------
// Prep: per 32 rows, (a) strictly-sequential fp32 sum-of-squares (reference
// order — unroll batches LDS loads, FADD chain order preserved), (b) fp16
// conversion (w scaled x1024). which=1 -> z.
// ---------------------------------------------------------------------------
__global__ void prep_kernel(const float* __restrict__ x, int which) {
    __shared__ float buf[32][257];
    int r0 = blockIdx.x * 32;
    const float scl = which ? 1.0f : 1024.0f;
    __half* dst = which ? g_Azh : g_Bwh;
    for (int i = threadIdx.x; i < 32 * 64; i += 256) {   // 32 rows x 64 float4
        int r = i >> 6, q = (i & 63) * 4;
        float4 v = *(const float4*)&x[(size_t)(r0 + r) * D + q];
        float* b = &buf[r][q];
        b[0] = v.x; b[1] = v.y; b[2] = v.z; b[3] = v.w;
        union { __half h[4]; uint2 u; } p;
        p.h[0] = __float2half(v.x * scl); p.h[1] = __float2half(v.y * scl);
        p.h[2] = __float2half(v.z * scl); p.h[3] = __float2half(v.w * scl);
        *(uint2*)&dst[(size_t)(r0 + r) * D + q] = p.u;
    }
    __syncthreads();
    if (threadIdx.x < 32) {
        int r = threadIdx.x;
        float a = 0.0f;
        #pragma unroll 8
        for (int c = 0; c < 256; ++c) {
            float v = buf[r][c];
            a = __fadd_rn(a, __fmul_rn(v, v));   // order preserved (IEEE ops)
        }
        if (which) g_A[r0 + r] = a;
        else       g_C[r0 + r] = a;
    }
}

// ---------------------------------------------------------------------------
// B slab loader: slab u -> chunk n = u/4, ks = u%4.
// 128 code rows x 64 fp16 (128B), SW128 into ring buffer (u&3).
// ---------------------------------------------------------------------------
__device__ __forceinline__ void load_Bslab(uint32_t sb, int u, int tid) {
    int n = u >> 2, ks = u & 3;
    size_t src0 = (size_t)(n * 128) * 512 + ks * 128;   // row = 512 bytes
    uint32_t dst0 = sb + SM_B + (u & 3) * 16384;
    #pragma unroll
    for (int it = 0; it < 4; ++it) {                 // 1024 chunks / 256 thr
        int i = tid + it * 256;
        int row = i >> 3, sub = i & 7;
        cp_async16(dst0 + SWZ(row * 128 + sub * 16),
                   (const char*)g_Bwh + src0 + (size_t)row * 512 + sub * 16);
    }
}

// ---------------------------------------------------------------------------
// Fused fp16 HMMA GEMM + argmin (+ fp16 dist-A store + 2nd-best flagging).
// CTA = 64 tokens, 256 threads (2x4 warps, 32x32 warp tiles). K=256.
// 2 CTAs/SM: 96KB smem + 128 regs/thread each.
// ---------------------------------------------------------------------------
__global__ void __launch_bounds__(256, 2)
vq_hmma_kernel(int nch) {
    extern __shared__ __align__(1024) char smem[];
    uint32_t sb = smem_u32(smem);
    const int tid = threadIdx.x;
    const int l   = tid & 31, w = tid >> 5;
    const int wm  = w >> 2,  wn = w & 3;
    const int bt0 = blockIdx.x * 64;
    const int nslab = nch * 4;

    // group 0: full A (4 slabs x 64 rows x 128B = 32KB) + B slab 0
    #pragma unroll
    for (int it = 0; it < 8; ++it) {                 // 2048 chunks / 256 thr
        int i = tid + it * 256;
        int r = i >> 9, rem = i & 511;
        int row = rem >> 3, sub = rem & 7;
        cp_async16(sb + r * 8192 + SWZ(row * 128 + sub * 16),
                   (const char*)g_Azh + (size_t)(bt0 + row) * 512 + r * 128 + sub * 16);
    }
    load_Bslab(sb, 0, tid);
    asm volatile("cp.async.commit_group;" ::: "memory");
    load_Bslab(sb, 1, tid);
    asm volatile("cp.async.commit_group;" ::: "memory");
    load_Bslab(sb, 2, tid);
    asm volatile("cp.async.commit_group;" ::: "memory");

    float Ar[2][2];
    #pragma unroll
    for (int mt = 0; mt < 2; ++mt)
        #pragma unroll
        for (int h = 0; h < 2; ++h)
            Ar[mt][h] = g_A[bt0 + wm * 32 + mt * 16 + h * 8 + (l >> 2)];

    float bd[2][2], bd2[2][2];
    int   bi[2][2];
    #pragma unroll
    for (int mt = 0; mt < 2; ++mt)
        #pragma unroll
        for (int h = 0; h < 2; ++h) {
            bd[mt][h] = __int_as_float(0x7f800000);
            bd2[mt][h] = __int_as_float(0x7f800000);
            bi[mt][h] = 0;
        }

    float acc[2][4][4];
    #pragma unroll
    for (int mt = 0; mt < 2; ++mt)
        #pragma unroll
        for (int nt = 0; nt < 4; ++nt)
            #pragma unroll
            for (int e = 0; e < 4; ++e) acc[mt][nt][e] = 0.0f;

    for (int u = 0; u < nslab; ++u) {
        if (u + 3 < nslab)
            asm volatile("cp.async.wait_group 2;" ::: "memory");
        else
            asm volatile("cp.async.wait_group 0;" ::: "memory");
        __syncthreads();

        if (u + 3 < nslab) {
            load_Bslab(sb, u + 3, tid);
            asm volatile("cp.async.commit_group;" ::: "memory");
        }

        const int ks = u & 3, n = u >> 2;
        const uint32_t abase = sb + ks * 8192;
        const uint32_t bbase = sb + SM_B + (u & 3) * 16384;

        #pragma unroll
        for (int kq = 0; kq < 2; ++kq) {
            uint32_t Bk[4][4];
            #pragma unroll
            for (int nt = 0; nt < 4; ++nt) {
                uint32_t ba = bbase +
                    SWZ((wn * 32 + nt * 8 + (l & 7)) * 128 + kq * 64 + (l >> 3) * 16);
                ldsm4(ba, Bk[nt]);
            }
            uint32_t Aa[2][2][4];
            #pragma unroll
            for (int mt = 0; mt < 2; ++mt)
                #pragma unroll
                for (int kk = 0; kk < 2; ++kk) {
                    uint32_t aa = abase +
                        SWZ((wm * 32 + mt * 16 + (l & 15)) * 128
                            + kq * 64 + kk * 32 + (l >> 4) * 16);
                    ldsm4(aa, Aa[mt][kk]);
                }
            #pragma unroll
            for (int mt = 0; mt < 2; ++mt)
                #pragma unroll
                for (int nt = 0; nt < 4; ++nt) {
                    mma_f16(acc[mt][nt], Aa[mt][0], Bk[nt][0], Bk[nt][1]);
                    mma_f16(acc[mt][nt], Aa[mt][1], Bk[nt][2], Bk[nt][3]);
                }
        }

        if (ks == 3) {
            // chunk epilogue: q = fl(fl(A - 2d) + C); store fp16(q - A)
            // (Sterbenz-exact subtraction); fold first-min + second-best
            #pragma unroll
            for (int mt = 0; mt < 2; ++mt)
                #pragma unroll
                for (int h = 0; h < 2; ++h) {
                    const int trow = wm * 32 + mt * 16 + h * 8 + (l >> 2);
                    #pragma unroll
                    for (int nt = 0; nt < 4; ++nt) {
                        int c0 = n * 128 + wn * 32 + nt * 8 + (l & 3) * 2;
                        float C0 = __ldg(&g_C[c0]);
                        float C1 = __ldg(&g_C[c0 + 1]);
                        float q0 = __fadd_rn(__fadd_rn(Ar[mt][h],
                                     acc[mt][nt][h * 2 + 0] * -0.001953125f), C0);
                        float q1 = __fadd_rn(__fadd_rn(Ar[mt][h],
                                     acc[mt][nt][h * 2 + 1] * -0.001953125f), C1);
                        __half2 hv;
                        hv.x = __float2half(__fadd_rn(q0, -Ar[mt][h]));
                        hv.y = __float2half(__fadd_rn(q1, -Ar[mt][h]));
                        *(__half2*)&g_Dh[(size_t)(bt0 + trow) * NE + c0] = hv;
                        if (q0 < bd[mt][h]) { bd2[mt][h] = bd[mt][h]; bd[mt][h] = q0; bi[mt][h] = c0; }
                        else if (q0 < bd2[mt][h]) bd2[mt][h] = q0;
                        if (q1 < bd[mt][h]) { bd2[mt][h] = bd[mt][h]; bd[mt][h] = q1; bi[mt][h] = c0 + 1; }
                        else if (q1 < bd2[mt][h]) bd2[mt][h] = q1;
                    }
                }
            #pragma unroll
            for (int mt = 0; mt < 2; ++mt)
                #pragma unroll
                for (int nt = 0; nt < 4; ++nt)
                    #pragma unroll
                    for (int e = 0; e < 4; ++e) acc[mt][nt][e] = 0.0f;
        }
    }

    // cross-lane reduce over the 4 lanes sharing each token row
    #pragma unroll
    for (int mt = 0; mt < 2; ++mt)
        #pragma unroll
        for (int h = 0; h < 2; ++h)
            #pragma unroll
            for (int off = 1; off <= 2; off <<= 1) {
                float od  = __shfl_xor_sync(0xffffffffu, bd[mt][h], off);
                int   oi  = __shfl_xor_sync(0xffffffffu, bi[mt][h], off);
                float od2 = __shfl_xor_sync(0xffffffffu, bd2[mt][h], off);
                float mx  = fmaxf(bd[mt][h], od);
                bd2[mt][h] = fminf(fminf(bd2[mt][h], od2), mx);
                if (od < bd[mt][h] || (od == bd[mt][h] && oi < bi[mt][h])) {
                    bd[mt][h] = od; bi[mt][h] = oi;
                }
            }

    __syncthreads();                     // B ring dead; reuse for staging
    float* stD  = (float*)(smem + SM_B);
    int*   stI  = (int*)(smem + SM_B + 1024);
    float* stD2 = (float*)(smem + SM_B + 2048);
    if ((l & 3) == 0) {
        #pragma unroll
        for (int mt = 0; mt < 2; ++mt)
            #pragma unroll
            for (int h = 0; h < 2; ++h) {
                int t = wm * 32 + mt * 16 + h * 8 + (l >> 2);
                stD[t * 4 + wn]  = bd[mt][h];
                stI[t * 4 + wn]  = bi[mt][h];
                stD2[t * 4 + wn] = bd2[mt][h];
            }
    }
    __syncthreads();
    if (tid < 64) {
        float db = stD[tid * 4];
        int   ib = stI[tid * 4];
        float s2 = stD2[tid * 4];
        #pragma unroll
        for (int m = 1; m < 4; ++m) {
            float d = stD[tid * 4 + m];
            int   i = stI[tid * 4 + m];
            float d2 = stD2[tid * 4 + m];
            s2 = fminf(s2, d2);
            if (d < db || (d == db && i < ib)) { s2 = fminf(s2, db); db = d; ib = i; }
            else s2 = fminf(s2, d);
        }
        g_idx[bt0 + tid] = ib;
        g_bd[bt0 + tid]  = db;
        if (s2 - db < TAU) {                      // ambiguous: exact re-check
            int pos = atomicAdd(&g_nflag, 1);
            g_flag[pos] = bt0 + tid;
        }
    }
}

// ---------------------------------------------------------------------------
// Candidate-pruned exact refinement, MLP-32 scan + single-phase chains.
// Warp per flagged token: prefetch the full fp16 (dist-A) row (32 coalesced
// loads), threshold against (bd-A)+TAU_SCAN, assign global candidate ranks
// so all candidates run their exact chains concurrently in ONE phase.
// Chain arithmetic identical to the proven round-1 kernel; lexicographic
// (dist, idx) min.
// ---------------------------------------------------------------------------
__global__ void __launch_bounds__(256, 1)
vq_refine_kernel(const float* __restrict__ z, const float* __restrict__ w) {
    __shared__ float zs[8][256];
    const int lane = threadIdx.x & 31, wl = threadIdx.x >> 5;
    const int gw = blockIdx.x * 8 + wl;
    const int nwarp = gridDim.x * 8;
    const int nf = g_nflag;

    for (int it = gw; it < nf; it += nwarp) {
        const int t = g_flag[it];
        const __half* drow = g_Dh + (size_t)t * NE;

        // MLP-32 prefetch of the full relative-dist row
        float dv[32];
        #pragma unroll
        for (int i = 0; i < 32; ++i) dv[i] = __half2float(drow[i * 32 + lane]);

        float* zr = zs[wl];
        #pragma unroll
        for (int q = 0; q < 2; ++q) {             // coalesced float4 loads
            float4 v = *(const float4*)&z[(size_t)t * D + (lane + q * 32) * 4];
            zr[(lane + q * 32) * 4 + 0] = v.x;
            zr[(lane + q * 32) * 4 + 1] = v.y;
            zr[(lane + q * 32) * 4 + 2] = v.z;
            zr[(lane + q * 32) * 4 + 3] = v.w;
        }
        __syncwarp();
        const float A   = g_A[t];
        const float thr = __fadd_rn(g_bd[t], -A) + TAU_SCAN;  // relative thr

        float bestd = __int_as_float(0x7f800000);
        int   besti = 0x7fffffff;

        int done = 0;
        while (true) {
            // assign candidates with global ranks [done, done+32) to lanes
            int myc = -1, seen = 0;
            #pragma unroll
            for (int i = 0; i < 32; ++i) {
                unsigned m = __ballot_sync(0xffffffffu, dv[i] < thr);
                int nc = __popc(m);
                int r = lane + done - seen;        // my rank within chunk i
                if (r >= 0 && r < nc) {
                    unsigned mm = m;
                    for (int k = 0; k < r; ++k) mm &= mm - 1;
                    myc = i * 32 + __ffs(mm) - 1;
                }
                seen += nc;
            }
            if (myc >= 0) {                        // one exact chain per lane
                float acc = 0.0f;
                const float* wr = w + (size_t)myc * D;
                #pragma unroll 8
                for (int k = 0; k < 256; ++k)      // exact sequential chain
                    acc = fmaf(zr[k], __ldg(&wr[k]), acc);
                float dist = __fadd_rn(__fadd_rn(A, -2.0f * acc), __ldg(&g_C[myc]));
                if (dist < bestd || (dist == bestd && myc < besti)) {
                    bestd = dist; besti = myc;
                }
            }
            done += 32;
            if (done >= seen) break;               // usually one phase
        }

        #pragma unroll
        for (int off = 16; off > 0; off >>= 1) {
            float od = __shfl_xor_sync(0xffffffffu, bestd, off);
            int   oi = __shfl_xor_sync(0xffffffffu, besti, off);
            if (od < bestd || (od == bestd && oi < besti)) { bestd = od; besti = oi; }
        }
        if (lane == 0) g_idx[t] = besti;
        __syncwarp();
    }
}

// ---------------------------------------------------------------------------
// Output: warp per 4 tokens (prefetched indices + grouped loads for MLP).
// z_q_st = fl(z + fl(zq-z)); loss = fl(m + fl(.25m))
// ---------------------------------------------------------------------------
__global__ void vq_out_kernel(const float* __restrict__ z, const float* __restrict__ w,
                              float* __restrict__ out_zq, float* __restrict__ out_loss,
                              float* __restrict__ out_idx) {
    int warp = threadIdx.x >> 5, lane = threadIdx.x & 31;
    int t0 = (blockIdx.x * 8 + warp) * 4;

    int j[4];
    #pragma unroll
    for (int i = 0; i < 4; ++i) j[i] = __ldg(&g_idx[t0 + i]);

    float4 zv[4][2], wv[4][2];
    #pragma unroll
    for (int i = 0; i < 4; ++i) {
        const float4* zp = (const float4*)(z + (size_t)(t0 + i) * D);
        const float4* wp = (const float4*)(w + (size_t)j[i] * D);
        #pragma unroll
        for (int q = 0; q < 2; ++q) {
            zv[i][q] = zp[lane + 32 * q];
            wv[i][q] = wp[lane + 32 * q];
        }
    }

    #pragma unroll
    for (int i = 0; i < 4; ++i) {
        float4* op = (float4*)(out_zq + (size_t)(t0 + i) * D);
        float sq = 0.0f;
        #pragma unroll
        for (int q = 0; q < 2; ++q) {
            float4 o;
            float d;
            d = __fadd_rn(wv[i][q].x, -zv[i][q].x); o.x = __fadd_rn(zv[i][q].x, d); sq = __fadd_rn(sq, __fmul_rn(d, d));
            d = __fadd_rn(wv[i][q].y, -zv[i][q].y); o.y = __fadd_rn(zv[i][q].y, d); sq = __fadd_rn(sq, __fmul_rn(d, d));
            d = __fadd_rn(wv[i][q].z, -zv[i][q].z); o.z = __fadd_rn(zv[i][q].z, d); sq = __fadd_rn(sq, __fmul_rn(d, d));
            d = __fadd_rn(wv[i][q].w, -zv[i][q].w); o.w = __fadd_rn(zv[i][q].w, d); sq = __fadd_rn(sq, __fmul_rn(d, d));
            op[lane + 32 * q] = o;
        }
        #pragma unroll
        for (int o = 16; o > 0; o >>= 1) sq += __shfl_xor_sync(0xffffffffu, sq, o);
        if (lane == 0) {
            float m = sq * (1.0f / 256.0f);
            out_loss[t0 + i] = __fadd_rn(m, __fmul_rn(0.25f, m));
            out_idx[t0 + i]  = (float)j[i];
        }
    }
}

// ---------------------------------------------------------------------------
extern "C" void kernel_launch(void* const* d_in, const int* in_sizes, int n_in,
                              void* d_out, int out_size) {
    const float* z = (const float*)d_in[0];
    const float* w = (const float*)d_in[1];
    const int n  = in_sizes[0] / D;   // 65536
    const int ne = in_sizes[1] / D;   // 1024
    float* out      = (float*)d_out;
    float* out_loss = out + (size_t)n * D;
    float* out_idx  = out_loss + n;

    reset_kernel<<<1, 1>>>();                       // #1
    prep_kernel<<<n / 32, 256>>>(z, 1);             // #2
    prep_kernel<<<ne / 32, 256>>>(w, 0);            // #3

    cudaFuncSetAttribute(vq_hmma_kernel,
                         cudaFuncAttributeMaxDynamicSharedMemorySize, SM_TOT);
    vq_hmma_kernel<<<n / 64, 256, SM_TOT>>>(ne / 128);   // #4: profiled

    vq_refine_kernel<<<1024, 256>>>(z, w);

    vq_out_kernel<<<n / 32, 256>>>(z, w, out, out_loss, out_idx);
}

// round 17
// speedup vs baseline: 5.2649x; 1.0247x over previous
#include <cuda_runtime.h>
#include <cuda_fp16.h>
#include <stdint.h>
#include <math.h>

// VectorQuantizer: z [65536,256] f32, W [1024,256] f32.
// dist = ||z||^2 - 2 z.W^T + ||w||^2 ; idx = argmin (first-min tie-break)
// out (f32): z_q_st [N*256] | loss [N] | idx [N]
//
// fp16 HMMA (K=256, w scaled x1024) computes ALL dists, tracks per-token
// best/second-best (fp32), and stores dist-A as fp16 (Sterbenz: q-A exact
// in fp32; fp16 quantization <= 3e-5). Worst-case fp16 dist error 6.2e-4;
// flag TAU = 7e-4 (fp32 q's). Refine scan threshold TAU_SCAN = 8e-4 >=
// 2*(err+qerr) keeps the candidate set a provable superset of the true
// argmin; candidates recomputed with the exact sequential fp32 chain of
// the proven round-1 kernel; first-min tie-break.

#define D    256
#define NTOK 65536
#define NE   1024
#define TAU      7e-4f
#define TAU_SCAN 8e-4f

__device__ float g_A[NTOK];
__device__ float g_C[NE];
__device__ float g_bd[NTOK];
__device__ int   g_idx[NTOK];
__device__ int   g_nflag;
__device__ int   g_flag[NTOK];
__device__ __align__(256) __half g_Dh[(size_t)NTOK * NE];  // dist - A (fp16)
__device__ __align__(256) __half g_Azh[(size_t)NTOK * D];
__device__ __align__(256) __half g_Bwh[(size_t)NE * D];

// smem: A resident 4 slabs x 8KB (SW128) + B ring 4 x 16KB
#define SM_B   32768
#define SM_TOT 98304
#define SWZ(o) ((o) ^ (((o) >> 3) & 0x70))

__device__ __forceinline__ uint32_t smem_u32(const void* p) {
    uint32_t a;
    asm("{ .reg .u64 t; cvta.to.shared.u64 t, %1; cvt.u32.u64 %0, t; }" : "=r"(a) : "l"(p));
    return a;
}
__device__ __forceinline__ void cp_async16(uint32_t dst, const void* src) {
    asm volatile("cp.async.cg.shared.global [%0], [%1], 16;" :: "r"(dst), "l"(src) : "memory");
}
__device__ __forceinline__ void ldsm4(uint32_t a, uint32_t r[4]) {
    asm volatile("ldmatrix.sync.aligned.m8n8.x4.shared.b16 {%0,%1,%2,%3}, [%4];"
                 : "=r"(r[0]), "=r"(r[1]), "=r"(r[2]), "=r"(r[3]) : "r"(a));
}
__device__ __forceinline__ void mma_f16(float d[4], const uint32_t a[4],
                                        uint32_t b0, uint32_t b1) {
    asm volatile(
        "mma.sync.aligned.m16n8k16.row.col.f32.f16.f16.f32 "
        "{%0,%1,%2,%3}, {%4,%5,%6,%7}, {%8,%9}, {%0,%1,%2,%3};"
        : "+f"(d[0]), "+f"(d[1]), "+f"(d[2]), "+f"(d[3])
        : "r"(a[0]), "r"(a[1]), "r"(a[2]), "r"(a[3]), "r"(b0), "r"(b1));
}

// ---------------------------------------------------------------------------
__global__ void reset_kernel() { g_nflag = 0; }

// ---------------------------------------------------------------------------
// Prep: per 32 rows, (a) strictly-sequential fp32 sum-of-squares (reference
// order — unroll batches LDS loads, FADD chain order preserved), (b) fp16
// conversion (w scaled x1024). which=1 -> z.
// ---------------------------------------------------------------------------
__global__ void prep_kernel(const float* __restrict__ x, int which) {
    __shared__ float buf[32][257];
    int r0 = blockIdx.x * 32;
    const float scl = which ? 1.0f : 1024.0f;
    __half* dst = which ? g_Azh : g_Bwh;
    for (int i = threadIdx.x; i < 32 * 64; i += 256) {   // 32 rows x 64 float4
        int r = i >> 6, q = (i & 63) * 4;
        float4 v = *(const float4*)&x[(size_t)(r0 + r) * D + q];
        float* b = &buf[r][q];
        b[0] = v.x; b[1] = v.y; b[2] = v.z; b[3] = v.w;
        union { __half h[4]; uint2 u; } p;
        p.h[0] = __float2half(v.x * scl); p.h[1] = __float2half(v.y * scl);
        p.h[2] = __float2half(v.z * scl); p.h[3] = __float2half(v.w * scl);
        *(uint2*)&dst[(size_t)(r0 + r) * D + q] = p.u;
    }
    __syncthreads();
    if (threadIdx.x < 32) {
        int r = threadIdx.x;
        float a = 0.0f;
        #pragma unroll 8
        for (int c = 0; c < 256; ++c) {
            float v = buf[r][c];
            a = __fadd_rn(a, __fmul_rn(v, v));   // order preserved (IEEE ops)
        }
        if (which) g_A[r0 + r] = a;
        else       g_C[r0 + r] = a;
    }
}

// ---------------------------------------------------------------------------
// B slab loader: slab u -> chunk n = u/4, ks = u%4.
// 128 code rows x 64 fp16 (128B), SW128 into ring buffer (u&3).
// ---------------------------------------------------------------------------
__device__ __forceinline__ void load_Bslab(uint32_t sb, int u, int tid) {
    int n = u >> 2, ks = u & 3;
    size_t src0 = (size_t)(n * 128) * 512 + ks * 128;   // row = 512 bytes
    uint32_t dst0 = sb + SM_B + (u & 3) * 16384;
    #pragma unroll
    for (int it = 0; it < 4; ++it) {                 // 1024 chunks / 256 thr
        int i = tid + it * 256;
        int row = i >> 3, sub = i & 7;
        cp_async16(dst0 + SWZ(row * 128 + sub * 16),
                   (const char*)g_Bwh + src0 + (size_t)row * 512 + sub * 16);
    }
}

// ---------------------------------------------------------------------------
// Fused fp16 HMMA GEMM + argmin (+ fp16 dist-A store + 2nd-best flagging).
// CTA = 64 tokens, 256 threads (2x4 warps, 32x32 warp tiles). K=256.
// 2 CTAs/SM. PAIR-granularity pipeline: one barrier + one wait per 2 slabs;
// pair p+1's buffers {(2p+2)&3,(2p+3)&3} are disjoint from pair p's and
// were last read by pair p-1, retired by the sync at the top of pair p.
// ---------------------------------------------------------------------------
__global__ void __launch_bounds__(256, 2)
vq_hmma_kernel(int nch) {
    extern __shared__ __align__(1024) char smem[];
    uint32_t sb = smem_u32(smem);
    const int tid = threadIdx.x;
    const int l   = tid & 31, w = tid >> 5;
    const int wm  = w >> 2,  wn = w & 3;
    const int bt0 = blockIdx.x * 64;
    const int npair = nch * 2;

    // preload: full A (4 slabs x 64 rows x 128B = 32KB) + B pair 0
    #pragma unroll
    for (int it = 0; it < 8; ++it) {                 // 2048 chunks / 256 thr
        int i = tid + it * 256;
        int r = i >> 9, rem = i & 511;
        int row = rem >> 3, sub = rem & 7;
        cp_async16(sb + r * 8192 + SWZ(row * 128 + sub * 16),
                   (const char*)g_Azh + (size_t)(bt0 + row) * 512 + r * 128 + sub * 16);
    }
    load_Bslab(sb, 0, tid);
    load_Bslab(sb, 1, tid);
    asm volatile("cp.async.commit_group;" ::: "memory");

    float Ar[2][2];
    #pragma unroll
    for (int mt = 0; mt < 2; ++mt)
        #pragma unroll
        for (int h = 0; h < 2; ++h)
            Ar[mt][h] = g_A[bt0 + wm * 32 + mt * 16 + h * 8 + (l >> 2)];

    float bd[2][2], bd2[2][2];
    int   bi[2][2];
    #pragma unroll
    for (int mt = 0; mt < 2; ++mt)
        #pragma unroll
        for (int h = 0; h < 2; ++h) {
            bd[mt][h] = __int_as_float(0x7f800000);
            bd2[mt][h] = __int_as_float(0x7f800000);
            bi[mt][h] = 0;
        }

    float acc[2][4][4];
    #pragma unroll
    for (int mt = 0; mt < 2; ++mt)
        #pragma unroll
        for (int nt = 0; nt < 4; ++nt)
            #pragma unroll
            for (int e = 0; e < 4; ++e) acc[mt][nt][e] = 0.0f;

    for (int p = 0; p < npair; ++p) {
        asm volatile("cp.async.wait_group 0;" ::: "memory");
        __syncthreads();   // pair p ready; pair p-1 compute fully retired

        if (p + 1 < npair) {
            load_Bslab(sb, 2 * p + 2, tid);
            load_Bslab(sb, 2 * p + 3, tid);
            asm volatile("cp.async.commit_group;" ::: "memory");
        }

        #pragma unroll
        for (int e2 = 0; e2 < 2; ++e2) {
            const int s = 2 * p + e2;
            const int ks = s & 3, n = s >> 2;
            const uint32_t abase = sb + ks * 8192;
            const uint32_t bbase = sb + SM_B + (s & 3) * 16384;

            #pragma unroll
            for (int kq = 0; kq < 2; ++kq) {
                uint32_t Bk[4][4];
                #pragma unroll
                for (int nt = 0; nt < 4; ++nt) {
                    uint32_t ba = bbase +
                        SWZ((wn * 32 + nt * 8 + (l & 7)) * 128 + kq * 64 + (l >> 3) * 16);
                    ldsm4(ba, Bk[nt]);
                }
                uint32_t Aa[2][2][4];
                #pragma unroll
                for (int mt = 0; mt < 2; ++mt)
                    #pragma unroll
                    for (int kk = 0; kk < 2; ++kk) {
                        uint32_t aa = abase +
                            SWZ((wm * 32 + mt * 16 + (l & 15)) * 128
                                + kq * 64 + kk * 32 + (l >> 4) * 16);
                        ldsm4(aa, Aa[mt][kk]);
                    }
                #pragma unroll
                for (int mt = 0; mt < 2; ++mt)
                    #pragma unroll
                    for (int nt = 0; nt < 4; ++nt) {
                        mma_f16(acc[mt][nt], Aa[mt][0], Bk[nt][0], Bk[nt][1]);
                        mma_f16(acc[mt][nt], Aa[mt][1], Bk[nt][2], Bk[nt][3]);
                    }
            }

            if (ks == 3) {
                // chunk epilogue: q = fl(fl(A - 2d) + C); store fp16(q - A)
                // (Sterbenz-exact subtraction); fold first-min + second-best
                #pragma unroll
                for (int mt = 0; mt < 2; ++mt)
                    #pragma unroll
                    for (int h = 0; h < 2; ++h) {
                        const int trow = wm * 32 + mt * 16 + h * 8 + (l >> 2);
                        #pragma unroll
                        for (int nt = 0; nt < 4; ++nt) {
                            int c0 = n * 128 + wn * 32 + nt * 8 + (l & 3) * 2;
                            float C0 = __ldg(&g_C[c0]);
                            float C1 = __ldg(&g_C[c0 + 1]);
                            float q0 = __fadd_rn(__fadd_rn(Ar[mt][h],
                                         acc[mt][nt][h * 2 + 0] * -0.001953125f), C0);
                            float q1 = __fadd_rn(__fadd_rn(Ar[mt][h],
                                         acc[mt][nt][h * 2 + 1] * -0.001953125f), C1);
                            __half2 hv;
                            hv.x = __float2half(__fadd_rn(q0, -Ar[mt][h]));
                            hv.y = __float2half(__fadd_rn(q1, -Ar[mt][h]));
                            *(__half2*)&g_Dh[(size_t)(bt0 + trow) * NE + c0] = hv;
                            if (q0 < bd[mt][h]) { bd2[mt][h] = bd[mt][h]; bd[mt][h] = q0; bi[mt][h] = c0; }
                            else if (q0 < bd2[mt][h]) bd2[mt][h] = q0;
                            if (q1 < bd[mt][h]) { bd2[mt][h] = bd[mt][h]; bd[mt][h] = q1; bi[mt][h] = c0 + 1; }
                            else if (q1 < bd2[mt][h]) bd2[mt][h] = q1;
                        }
                    }
                #pragma unroll
                for (int mt = 0; mt < 2; ++mt)
                    #pragma unroll
                    for (int nt = 0; nt < 4; ++nt)
                        #pragma unroll
                        for (int e = 0; e < 4; ++e) acc[mt][nt][e] = 0.0f;
            }
        }
    }

    // cross-lane reduce over the 4 lanes sharing each token row
    #pragma unroll
    for (int mt = 0; mt < 2; ++mt)
        #pragma unroll
        for (int h = 0; h < 2; ++h)
            #pragma unroll
            for (int off = 1; off <= 2; off <<= 1) {
                float od  = __shfl_xor_sync(0xffffffffu, bd[mt][h], off);
                int   oi  = __shfl_xor_sync(0xffffffffu, bi[mt][h], off);
                float od2 = __shfl_xor_sync(0xffffffffu, bd2[mt][h], off);
                float mx  = fmaxf(bd[mt][h], od);
                bd2[mt][h] = fminf(fminf(bd2[mt][h], od2), mx);
                if (od < bd[mt][h] || (od == bd[mt][h] && oi < bi[mt][h])) {
                    bd[mt][h] = od; bi[mt][h] = oi;
                }
            }

    __syncthreads();                     // B ring dead; reuse for staging
    float* stD  = (float*)(smem + SM_B);
    int*   stI  = (int*)(smem + SM_B + 1024);
    float* stD2 = (float*)(smem + SM_B + 2048);
    if ((l & 3) == 0) {
        #pragma unroll
        for (int mt = 0; mt < 2; ++mt)
            #pragma unroll
            for (int h = 0; h < 2; ++h) {
                int t = wm * 32 + mt * 16 + h * 8 + (l >> 2);
                stD[t * 4 + wn]  = bd[mt][h];
                stI[t * 4 + wn]  = bi[mt][h];
                stD2[t * 4 + wn] = bd2[mt][h];
            }
    }
    __syncthreads();
    if (tid < 64) {
        float db = stD[tid * 4];
        int   ib = stI[tid * 4];
        float s2 = stD2[tid * 4];
        #pragma unroll
        for (int m = 1; m < 4; ++m) {
            float d = stD[tid * 4 + m];
            int   i = stI[tid * 4 + m];
            float d2 = stD2[tid * 4 + m];
            s2 = fminf(s2, d2);
            if (d < db || (d == db && i < ib)) { s2 = fminf(s2, db); db = d; ib = i; }
            else s2 = fminf(s2, d);
        }
        g_idx[bt0 + tid] = ib;
        g_bd[bt0 + tid]  = db;
        if (s2 - db < TAU) {                      // ambiguous: exact re-check
            int pos = atomicAdd(&g_nflag, 1);
            g_flag[pos] = bt0 + tid;
        }
    }
}

// ---------------------------------------------------------------------------
// Candidate-pruned exact refinement, MLP-32 scan + single-phase chains.
// Warp per flagged token: prefetch the full fp16 (dist-A) row (32 coalesced
// loads), threshold against (bd-A)+TAU_SCAN, assign global candidate ranks
// so all candidates run their exact chains concurrently in ONE phase.
// Chain arithmetic identical to the proven round-1 kernel; lexicographic
// (dist, idx) min.
// ---------------------------------------------------------------------------
__global__ void __launch_bounds__(256, 1)
vq_refine_kernel(const float* __restrict__ z, const float* __restrict__ w) {
    __shared__ float zs[8][256];
    const int lane = threadIdx.x & 31, wl = threadIdx.x >> 5;
    const int gw = blockIdx.x * 8 + wl;
    const int nwarp = gridDim.x * 8;
    const int nf = g_nflag;

    for (int it = gw; it < nf; it += nwarp) {
        const int t = g_flag[it];
        const __half* drow = g_Dh + (size_t)t * NE;

        // MLP-32 prefetch of the full relative-dist row
        float dv[32];
        #pragma unroll
        for (int i = 0; i < 32; ++i) dv[i] = __half2float(drow[i * 32 + lane]);

        float* zr = zs[wl];
        #pragma unroll
        for (int q = 0; q < 2; ++q) {             // coalesced float4 loads
            float4 v = *(const float4*)&z[(size_t)t * D + (lane + q * 32) * 4];
            zr[(lane + q * 32) * 4 + 0] = v.x;
            zr[(lane + q * 32) * 4 + 1] = v.y;
            zr[(lane + q * 32) * 4 + 2] = v.z;
            zr[(lane + q * 32) * 4 + 3] = v.w;
        }
        __syncwarp();
        const float A   = g_A[t];
        const float thr = __fadd_rn(g_bd[t], -A) + TAU_SCAN;  // relative thr

        float bestd = __int_as_float(0x7f800000);
        int   besti = 0x7fffffff;

        int done = 0;
        while (true) {
            // assign candidates with global ranks [done, done+32) to lanes
            int myc = -1, seen = 0;
            #pragma unroll
            for (int i = 0; i < 32; ++i) {
                unsigned m = __ballot_sync(0xffffffffu, dv[i] < thr);
                int nc = __popc(m);
                int r = lane + done - seen;        // my rank within chunk i
                if (r >= 0 && r < nc) {
                    unsigned mm = m;
                    for (int k = 0; k < r; ++k) mm &= mm - 1;
                    myc = i * 32 + __ffs(mm) - 1;
                }
                seen += nc;
            }
            if (myc >= 0) {                        // one exact chain per lane
                float acc = 0.0f;
                const float* wr = w + (size_t)myc * D;
                #pragma unroll 8
                for (int k = 0; k < 256; ++k)      // exact sequential chain
                    acc = fmaf(zr[k], __ldg(&wr[k]), acc);
                float dist = __fadd_rn(__fadd_rn(A, -2.0f * acc), __ldg(&g_C[myc]));
                if (dist < bestd || (dist == bestd && myc < besti)) {
                    bestd = dist; besti = myc;
                }
            }
            done += 32;
            if (done >= seen) break;               // usually one phase
        }

        #pragma unroll
        for (int off = 16; off > 0; off >>= 1) {
            float od = __shfl_xor_sync(0xffffffffu, bestd, off);
            int   oi = __shfl_xor_sync(0xffffffffu, besti, off);
            if (od < bestd || (od == bestd && oi < besti)) { bestd = od; besti = oi; }
        }
        if (lane == 0) g_idx[t] = besti;
        __syncwarp();
    }
}

// ---------------------------------------------------------------------------
// Output: warp per 4 tokens (prefetched indices + grouped loads for MLP).
// z_q_st = fl(z + fl(zq-z)); loss = fl(m + fl(.25m))
// ---------------------------------------------------------------------------
__global__ void vq_out_kernel(const float* __restrict__ z, const float* __restrict__ w,
                              float* __restrict__ out_zq, float* __restrict__ out_loss,
                              float* __restrict__ out_idx) {
    int warp = threadIdx.x >> 5, lane = threadIdx.x & 31;
    int t0 = (blockIdx.x * 8 + warp) * 4;

    int j[4];
    #pragma unroll
    for (int i = 0; i < 4; ++i) j[i] = __ldg(&g_idx[t0 + i]);

    float4 zv[4][2], wv[4][2];
    #pragma unroll
    for (int i = 0; i < 4; ++i) {
        const float4* zp = (const float4*)(z + (size_t)(t0 + i) * D);
        const float4* wp = (const float4*)(w + (size_t)j[i] * D);
        #pragma unroll
        for (int q = 0; q < 2; ++q) {
            zv[i][q] = zp[lane + 32 * q];
            wv[i][q] = wp[lane + 32 * q];
        }
    }

    #pragma unroll
    for (int i = 0; i < 4; ++i) {
        float4* op = (float4*)(out_zq + (size_t)(t0 + i) * D);
        float sq = 0.0f;
        #pragma unroll
        for (int q = 0; q < 2; ++q) {
            float4 o;
            float d;
            d = __fadd_rn(wv[i][q].x, -zv[i][q].x); o.x = __fadd_rn(zv[i][q].x, d); sq = __fadd_rn(sq, __fmul_rn(d, d));
            d = __fadd_rn(wv[i][q].y, -zv[i][q].y); o.y = __fadd_rn(zv[i][q].y, d); sq = __fadd_rn(sq, __fmul_rn(d, d));
            d = __fadd_rn(wv[i][q].z, -zv[i][q].z); o.z = __fadd_rn(zv[i][q].z, d); sq = __fadd_rn(sq, __fmul_rn(d, d));
            d = __fadd_rn(wv[i][q].w, -zv[i][q].w); o.w = __fadd_rn(zv[i][q].w, d); sq = __fadd_rn(sq, __fmul_rn(d, d));
            op[lane + 32 * q] = o;
        }
        #pragma unroll
        for (int o = 16; o > 0; o >>= 1) sq += __shfl_xor_sync(0xffffffffu, sq, o);
        if (lane == 0) {
            float m = sq * (1.0f / 256.0f);
            out_loss[t0 + i] = __fadd_rn(m, __fmul_rn(0.25f, m));
            out_idx[t0 + i]  = (float)j[i];
        }
    }
}

// ---------------------------------------------------------------------------
extern "C" void kernel_launch(void* const* d_in, const int* in_sizes, int n_in,
                              void* d_out, int out_size) {
    const float* z = (const float*)d_in[0];
    const float* w = (const float*)d_in[1];
    const int n  = in_sizes[0] / D;   // 65536
    const int ne = in_sizes[1] / D;   // 1024
    float* out      = (float*)d_out;
    float* out_loss = out + (size_t)n * D;
    float* out_idx  = out_loss + n;

    reset_kernel<<<1, 1>>>();                       // #1
    prep_kernel<<<n / 32, 256>>>(z, 1);             // #2
    prep_kernel<<<ne / 32, 256>>>(w, 0);            // #3

    cudaFuncSetAttribute(vq_hmma_kernel,
                         cudaFuncAttributeMaxDynamicSharedMemorySize, SM_TOT);
    vq_hmma_kernel<<<n / 64, 256, SM_TOT>>>(ne / 128);   // #4: profiled

    vq_refine_kernel<<<1024, 256>>>(z, w);

    vq_out_kernel<<<n / 32, 256>>>(z, w, out, out_loss, out_idx);
}